// round 14
// baseline (speedup 1.0000x reference)
#include <cuda_runtime.h>
#include <cuda_bf16.h>
#include <cstdint>

// Geometry:
//  stage0 in : [5][256][3][16][32]
//  stem out  : 16ch @16x32, NP0 = 5*256*512 = 655360
//  block1    : 64ch @8x16,  NP1 = 5*256*128 = 163840
//  block2    : 256ch@4x8,   NP2 = 5*256*32  = 40960
// ALL activations position-major: fp32 t[pos*C + c]; stem bf16 planes [pos][16]

#define NP0 655360
#define NP1 163840
#define NP2 40960

// ------------------------- device scratch ----------------------------------
__device__ float g_u1[64 * NP1];
__device__ float g_v1[64 * NP1];
__device__ float g_h1[64 * NP1];
__device__ float g_w1[64 * NP1];
__device__ float g_u2[256 * NP2];
__device__ float g_v2[256 * NP2];
__device__ float g_h2[256 * NP2];
__device__ float g_w2[256 * NP2];
__device__ float g_gmax[256 * 256];

__device__ float g_psum[1310720];
__device__ float g_psq [1310720];

__device__ float g_scale[1296];
__device__ float g_shift[1296];

// split bf16 weights (hex: k = chunk*64 + t*8 + cl, tap7 = 0)
__device__ __nv_bfloat16 g_whex_hi[256 * 2048];
__device__ __nv_bfloat16 g_whex_lo[256 * 2048];
__device__ __nv_bfloat16 g_wb1h_hi[64 * 512];
__device__ __nv_bfloat16 g_wb1h_lo[64 * 512];
__device__ __nv_bfloat16 g_went_hi[512 * 64];
__device__ __nv_bfloat16 g_went_lo[512 * 64];
__device__ __nv_bfloat16 g_wc3_hi [256 * 256];
__device__ __nv_bfloat16 g_wc3_lo [256 * 256];
__device__ __nv_bfloat16 g_wb1c3_hi[64 * 64];
__device__ __nv_bfloat16 g_wb1c3_lo[64 * 64];
// block1 entry: folded (bn1-scaled) weights [128 o][16 c] + bias
__device__ __nv_bfloat16 g_went2_hi[128 * 16];
__device__ __nv_bfloat16 g_went2_lo[128 * 16];
__device__ float g_bias2[128];

// stem bf16 activation planes [pos][16]
__device__ __nv_bfloat16 g_abf_hi[NP0 * 16];
__device__ __nv_bfloat16 g_abf_lo[NP0 * 16];

// ------------------------- mma helpers -------------------------------------
__device__ __forceinline__ uint32_t smem_u32(const void* p) {
    uint32_t a;
    asm("{ .reg .u64 t; cvta.to.shared.u64 t, %1; cvt.u32.u64 %0, t; }"
        : "=r"(a) : "l"(p));
    return a;
}
__device__ __forceinline__ void ldmA(uint32_t* a, uint32_t addr) {
    asm volatile("ldmatrix.sync.aligned.m8n8.x4.shared.b16 {%0,%1,%2,%3}, [%4];"
        : "=r"(a[0]), "=r"(a[1]), "=r"(a[2]), "=r"(a[3]) : "r"(addr));
}
__device__ __forceinline__ void ldmB(uint32_t* b, uint32_t addr) {
    asm volatile("ldmatrix.sync.aligned.m8n8.x2.shared.b16 {%0,%1}, [%2];"
        : "=r"(b[0]), "=r"(b[1]) : "r"(addr));
}
__device__ __forceinline__ void mma16816(float* d, const uint32_t* a, const uint32_t* b) {
    asm volatile(
        "mma.sync.aligned.m16n8k16.row.col.f32.bf16.bf16.f32 "
        "{%0,%1,%2,%3}, {%4,%5,%6,%7}, {%8,%9}, {%0,%1,%2,%3};"
        : "+f"(d[0]), "+f"(d[1]), "+f"(d[2]), "+f"(d[3])
        : "r"(a[0]), "r"(a[1]), "r"(a[2]), "r"(a[3]), "r"(b[0]), "r"(b[1]));
}

// ------------------------- prep kernels ------------------------------------
__global__ void hexsplit_k(const float* __restrict__ src,
                           __nv_bfloat16* __restrict__ hi, __nv_bfloat16* __restrict__ lo,
                           int O, int C) {
    int i = blockIdx.x * 256 + threadIdx.x;
    if (i < O * C * 8) {
        int t = i & 7;
        int c = (i >> 3) % C;
        int o = i / (8 * C);
        float w = (t < 7) ? src[(o * C + c) * 9 + t + 1] : 0.f;
        __nv_bfloat16 h = __float2bfloat16(w);
        int k = (c >> 3) * 64 + t * 8 + (c & 7);
        hi[(size_t)o * (C * 8) + k] = h;
        lo[(size_t)o * (C * 8) + k] = __float2bfloat16(w - __bfloat162float(h));
    }
}

__global__ void split1x1_k(const float* __restrict__ src,
                           __nv_bfloat16* __restrict__ hi, __nv_bfloat16* __restrict__ lo,
                           int O, int C, int rowoff) {
    int i = blockIdx.x * 256 + threadIdx.x;
    if (i < O * C) {
        float w = src[i];
        __nv_bfloat16 h = __float2bfloat16(w);
        int o = i / C, c = i % C;
        hi[(rowoff + o) * C + c] = h;
        lo[(rowoff + o) * C + c] = __float2bfloat16(w - __bfloat162float(h));
    }
}

// fold bn1 affine into block1-entry weights: w' = w*s_c, bias = sum w*t_c
__global__ void foldentry_k(const float* __restrict__ c1w, const float* __restrict__ dsw,
                            const float* __restrict__ sc0, const float* __restrict__ sh0,
                            __nv_bfloat16* __restrict__ hi, __nv_bfloat16* __restrict__ lo,
                            float* __restrict__ bias) {
    int o = threadIdx.x;  // 128
    const float* src = (o < 64) ? (c1w + o * 16) : (dsw + (o - 64) * 16);
    float b = 0.f;
    for (int c = 0; c < 16; c++) {
        float w = src[c] * sc0[c];
        b += src[c] * sh0[c];
        __nv_bfloat16 h = __float2bfloat16(w);
        hi[o * 16 + c] = h;
        lo[o * 16 + c] = __float2bfloat16(w - __bfloat162float(h));
    }
    bias[o] = b;
}

// ------------------------- stem: hexconv -> relu -> bf16 planes -------------
__global__ __launch_bounds__(256) void stem_kernel(
    const float* __restrict__ x, const float* __restrict__ wc,
    __nv_bfloat16* __restrict__ ahi, __nv_bfloat16* __restrict__ alo,
    float* __restrict__ psum, float* __restrict__ psq) {
    __shared__ float wsh[432];
    __shared__ float wpS[16][8], wpQ[16][8];
    int tid = threadIdx.x;
    for (int e = tid; e < 432; e += 256) wsh[e] = wc[e];
    __syncthreads();

    int pos = blockIdx.x * 256 + tid;
    int w = pos & 31, h = (pos >> 5) & 15, b = (pos >> 9) & 255, f = pos >> 17;

    float acc[16];
#pragma unroll
    for (int o = 0; o < 16; o++) acc[o] = 0.f;

#pragma unroll
    for (int t = 0; t < 7; t++) {
        int kf = t + 1;
        int dy = kf / 3 - 1, dx = kf % 3 - 1;
        int hh = h + dy;
        float xv0 = 0.f, xv1 = 0.f, xv2 = 0.f;
        if (hh >= 0 && hh < 16) {
            int ww = w + dx, ff = f;
            if (ww < 0)       { ff = (f + 4) % 5; ww = 31; }
            else if (ww > 31) { ff = (f + 1) % 5; ww = 0;  }
            int base = (ff * 256 + b) * 1536 + hh * 32 + ww;
            xv0 = x[base];
            xv1 = x[base + 512];
            xv2 = x[base + 1024];
        }
#pragma unroll
        for (int o = 0; o < 16; o++) {
            acc[o] += wsh[(o * 3 + 0) * 9 + kf] * xv0
                    + wsh[(o * 3 + 1) * 9 + kf] * xv1
                    + wsh[(o * 3 + 2) * 9 + kf] * xv2;
        }
    }

    __align__(16) __nv_bfloat16 h16[16];
    __align__(16) __nv_bfloat16 l16[16];
    int lane = tid & 31, warp = tid >> 5;
#pragma unroll
    for (int o = 0; o < 16; o++) {
        float val = fmaxf(acc[o], 0.f);
        __nv_bfloat16 hb = __float2bfloat16(val);
        h16[o] = hb;
        l16[o] = __float2bfloat16(val - __bfloat162float(hb));
        float s = val, q2 = val * val;
#pragma unroll
        for (int d = 16; d; d >>= 1) {
            s  += __shfl_xor_sync(0xFFFFFFFFu, s,  d);
            q2 += __shfl_xor_sync(0xFFFFFFFFu, q2, d);
        }
        if (lane == 0) { wpS[o][warp] = s; wpQ[o][warp] = q2; }
    }
    *(uint4*)(ahi + (size_t)pos * 16)     = *(uint4*)h16;
    *(uint4*)(ahi + (size_t)pos * 16 + 8) = *(uint4*)(h16 + 8);
    *(uint4*)(alo + (size_t)pos * 16)     = *(uint4*)l16;
    *(uint4*)(alo + (size_t)pos * 16 + 8) = *(uint4*)(l16 + 8);

    __syncthreads();
    if (tid < 16) {
        float s = 0.f, q = 0.f;
#pragma unroll
        for (int wpi = 0; wpi < 8; wpi++) { s += wpS[tid][wpi]; q += wpQ[tid][wpi]; }
        psum[blockIdx.x * 16 + tid] = s;
        psq [blockIdx.x * 16 + tid] = q;
    }
}

// ------------------------- BN param fold ------------------------------------
__global__ void bn_param(const float* __restrict__ ps, const float* __restrict__ pq,
                         int nparts, int cstride, int coff, float invN,
                         const float* __restrict__ g, const float* __restrict__ b,
                         float* __restrict__ sc, float* __restrict__ sh) {
    int c = blockIdx.x, tid = threadIdx.x;
    float s = 0.f, q = 0.f;
    for (int p = tid; p < nparts; p += 256) {
        s += ps[(size_t)p * cstride + coff + c];
        q += pq[(size_t)p * cstride + coff + c];
    }
    __shared__ float rs[256], rq[256];
    rs[tid] = s; rq[tid] = q;
    __syncthreads();
    for (int d = 128; d; d >>= 1) {
        if (tid < d) { rs[tid] += rs[tid + d]; rq[tid] += rq[tid + d]; }
        __syncthreads();
    }
    if (tid == 0) {
        float mean = rs[0] * invN;
        float var  = rq[0] * invN - mean * mean;
        float k = g[c] * rsqrtf(var + 1e-5f);
        sc[c] = k;
        sh[c] = b[c] - mean * k;
    }
}

// ---------------- generic mma.sync split-bf16 conv/GEMM ---------------------
// D[m=128, o=NTILE] = A[m, k] * W[o, k].
// AMODE 0: A from bf16 planes ahi/alo [pos][CDIM].
// AMODE 1: A = relu(scA*xf1+shA) fused at staging (fp32 [pos][CDIM]).
// AMODE 2: A = relu(scA*xf1+shA + scB*xf2+shB).
// Outputs POSITION-MAJOR fp32: oc<OSPLIT -> outU[q*CU+oc] else outV[q*CV+oc-OSPLIT].
// TAPS=7: k = chunk*64 + t*8 + cl; TAPS=1: k = c. KCH = min(KTOT,64).
template <int KTOT, int NTILE, int TAPS, bool POOL, int HIN, int WIN,
          int NSTR, int OSPLIT, int CDIM, int CU, int CV, int AMODE>
__global__ __launch_bounds__(256) void mma_conv_k(
    const __nv_bfloat16* __restrict__ ahi, const __nv_bfloat16* __restrict__ alo,
    const float* __restrict__ xf1, const float* __restrict__ xf2,
    const float* __restrict__ scA, const float* __restrict__ shA,
    const float* __restrict__ scB, const float* __restrict__ shB,
    const __nv_bfloat16* __restrict__ whi, const __nv_bfloat16* __restrict__ wlo,
    const float* __restrict__ bias,
    float* __restrict__ outU, float* __restrict__ outV,
    float* __restrict__ psum, float* __restrict__ psq) {
    constexpr int NT = NTILE / 8;
    constexpr int KCH = (KTOT < 64) ? KTOT : 64;
    constexpr int NCHUNK = KTOT / KCH;
    constexpr int LDAv = KCH + 8;
    constexpr int GPR = KCH / 8;
    constexpr int KS = KCH / 16;
    constexpr int AITERS = (128 * GPR) / 256;
    constexpr int BITERS = (NTILE * GPR + 255) / 256;
    constexpr int OF_SC = 3584;
    constexpr int OF_AH = OF_SC + 4 * CDIM * 4;
    constexpr int OF_AL = OF_AH + 128 * LDAv * 2;
    constexpr int OF_BH = OF_AL + 128 * LDAv * 2;
    constexpr int OF_BL = OF_BH + NTILE * LDAv * 2;
    constexpr int OF_PS = OF_BL + NTILE * LDAv * 2;
    constexpr int OF_PQ = OF_PS + NTILE * 32;

    extern __shared__ __align__(16) char smem[];
    uint32_t sb = smem_u32(smem);
    int tid = threadIdx.x;
    int wid = tid >> 5, lane = tid & 31;
    int q0 = blockIdx.x * 128;
    int o0 = blockIdx.y * NTILE;

    int* nbr = (int*)(smem);
    for (int e = tid; e < TAPS * 128; e += 256) {
        int t = e >> 7, ql = e & 127;
        int m = q0 + ql;
        int pos;
        if (POOL) {
            constexpr int WO = WIN / 2, HO = HIN / 2;
            int qq = m >> 2, sub = m & 3;
            int w = qq % WO;
            int h = (qq / WO) % HO;
            int fb = qq / (WO * HO);
            pos = (fb * HIN + 2 * h + (sub >> 1)) * WIN + 2 * w + (sub & 1);
        } else if (TAPS == 1) {
            pos = m;
        } else {
            int w = m % WIN;
            int h = (m / WIN) % HIN;
            int b = (m / (WIN * HIN)) & 255;
            int f = m / (WIN * HIN * 256);
            int kf = t + 1;
            int dy = kf / 3 - 1, dx = kf % 3 - 1;
            int hh = h + dy, ww = w + dx, ff = f;
            if (hh < 0 || hh >= HIN) pos = -1;
            else {
                if (ww < 0)        { ff = (f + 4) % 5; ww = WIN - 1; }
                else if (ww >= WIN){ ff = (f + 1) % 5; ww = 0;       }
                pos = ((ff * 256 + b) * HIN + hh) * WIN + ww;
            }
        }
        nbr[t * 128 + ql] = pos;
    }
    float* scS  = (float*)(smem + OF_SC);
    float* shS  = scS + CDIM;
    float* sc2S = shS + CDIM;
    float* sh2S = sc2S + CDIM;
    if (AMODE >= 1) {
        for (int c = tid; c < CDIM; c += 256) {
            scS[c] = scA[c];
            shS[c] = shA[c];
            if (AMODE == 2) { sc2S[c] = scB[c]; sh2S[c] = shB[c]; }
        }
    }
    __syncthreads();

    float acc[NT][4];
#pragma unroll
    for (int nt = 0; nt < NT; nt++)
#pragma unroll
        for (int j = 0; j < 4; j++) acc[nt][j] = 0.f;

    int m0 = wid * 16;
    int grp = lane >> 3;
    int rowA = m0 + (lane & 7) + (grp & 1) * 8;
    int colA8 = (grp >> 1) * 8;
    uint32_t aBaseH = sb + OF_AH + (uint32_t)(rowA * LDAv + colA8) * 2;
    uint32_t aBaseL = sb + OF_AL + (uint32_t)(rowA * LDAv + colA8) * 2;
    int rowB = (lane & 7);
    int colB8 = ((lane >> 3) & 1) * 8;
    uint32_t bBaseH = sb + OF_BH + (uint32_t)(rowB * LDAv + colB8) * 2;
    uint32_t bBaseL = sb + OF_BL + (uint32_t)(rowB * LDAv + colB8) * 2;

    __nv_bfloat16* AH = (__nv_bfloat16*)(smem + OF_AH);
    __nv_bfloat16* AL = (__nv_bfloat16*)(smem + OF_AL);
    __nv_bfloat16* BH = (__nv_bfloat16*)(smem + OF_BH);
    __nv_bfloat16* BL = (__nv_bfloat16*)(smem + OF_BL);

#pragma unroll 1
    for (int ci = 0; ci < NCHUNK; ci++) {
        // stage A: [128 m][KCH k]
#pragma unroll
        for (int it = 0; it < AITERS; it++) {
            int e = it * 256 + tid;
            int q = e / GPR, g = e % GPR;
            int pos = -1, c0;
            if (TAPS == 7) { c0 = ci * 8; if (g < 7) pos = nbr[g * 128 + q]; }
            else           { c0 = ci * KCH + g * 8; pos = nbr[q]; }
            if (AMODE == 0) {
                uint4 vh = {0u, 0u, 0u, 0u}, vl = {0u, 0u, 0u, 0u};
                if (pos >= 0) {
                    size_t base = (size_t)pos * CDIM + c0;
                    vh = *(const uint4*)(ahi + base);
                    vl = *(const uint4*)(alo + base);
                }
                *(uint4*)(AH + q * LDAv + g * 8) = vh;
                *(uint4*)(AL + q * LDAv + g * 8) = vl;
            } else {
                float v[8] = {0.f, 0.f, 0.f, 0.f, 0.f, 0.f, 0.f, 0.f};
                if (pos >= 0) {
                    const float* p1 = xf1 + (size_t)pos * CDIM + c0;
                    float4 f0 = *(const float4*)p1;
                    float4 f1 = *(const float4*)(p1 + 4);
                    float r1[8] = {f0.x, f0.y, f0.z, f0.w, f1.x, f1.y, f1.z, f1.w};
                    if (AMODE == 2) {
                        const float* p2 = xf2 + (size_t)pos * CDIM + c0;
                        float4 g0 = *(const float4*)p2;
                        float4 g1 = *(const float4*)(p2 + 4);
                        float r2[8] = {g0.x, g0.y, g0.z, g0.w, g1.x, g1.y, g1.z, g1.w};
#pragma unroll
                        for (int j = 0; j < 8; j++)
                            v[j] = fmaxf(scS[c0 + j] * r1[j] + shS[c0 + j]
                                       + sc2S[c0 + j] * r2[j] + sh2S[c0 + j], 0.f);
                    } else {
#pragma unroll
                        for (int j = 0; j < 8; j++)
                            v[j] = fmaxf(scS[c0 + j] * r1[j] + shS[c0 + j], 0.f);
                    }
                }
                __align__(16) __nv_bfloat16 h8[8], l8[8];
#pragma unroll
                for (int j = 0; j < 8; j++) {
                    __nv_bfloat16 hb = __float2bfloat16(v[j]);
                    h8[j] = hb;
                    l8[j] = __float2bfloat16(v[j] - __bfloat162float(hb));
                }
                *(uint4*)(AH + q * LDAv + g * 8) = *(uint4*)h8;
                *(uint4*)(AL + q * LDAv + g * 8) = *(uint4*)l8;
            }
        }
        // stage B: [NTILE o][KCH k]
#pragma unroll
        for (int it = 0; it < BITERS; it++) {
            int e = it * 256 + tid;
            if (e < NTILE * GPR) {
                int o = e / GPR, j = e % GPR;
                size_t src = (size_t)(o0 + o) * KTOT + ci * KCH + j * 8;
                *(uint4*)(BH + o * LDAv + j * 8) = *(const uint4*)(whi + src);
                *(uint4*)(BL + o * LDAv + j * 8) = *(const uint4*)(wlo + src);
            }
        }
        __syncthreads();

#pragma unroll
        for (int ks = 0; ks < KS; ks++) {
            uint32_t aH[4], aL[4];
            ldmA(aH, aBaseH + ks * 32);
            ldmA(aL, aBaseL + ks * 32);
#pragma unroll
            for (int nt = 0; nt < NT; nt++) {
                uint32_t bH[2], bL[2];
                uint32_t boff = (uint32_t)(nt * 8 * LDAv) * 2 + ks * 32;
                ldmB(bH, bBaseH + boff);
                ldmB(bL, bBaseL + boff);
                mma16816(acc[nt], aH, bH);
                mma16816(acc[nt], aL, bH);
                mma16816(acc[nt], aH, bL);
            }
        }
        __syncthreads();
    }

    float* pS = (float*)(smem + OF_PS);
    float* pQ = (float*)(smem + OF_PQ);

    if (!POOL) {
        int r = lane >> 2;
        int cp = (lane & 3) << 1;
#pragma unroll
        for (int nt = 0; nt < NT; nt++) {
            int c0c = nt * 8 + cp;
            int qrow = q0 + m0 + r;
            int oc0 = o0 + c0c;
            bool inU = (oc0 < OSPLIT);
            float* base = inU ? (outU + (size_t)qrow * CU + oc0)
                              : (outV + (size_t)qrow * CV + (oc0 - OSPLIT));
            int stride = inU ? CU : CV;
            base[0] = acc[nt][0];
            base[1] = acc[nt][1];
            base[8 * stride]     = acc[nt][2];
            base[8 * stride + 1] = acc[nt][3];
            float s0 = acc[nt][0] + acc[nt][2];
            float s1 = acc[nt][1] + acc[nt][3];
            float t0 = acc[nt][0]*acc[nt][0] + acc[nt][2]*acc[nt][2];
            float t1 = acc[nt][1]*acc[nt][1] + acc[nt][3]*acc[nt][3];
#pragma unroll
            for (int d = 4; d <= 16; d <<= 1) {
                s0 += __shfl_xor_sync(0xFFFFFFFFu, s0, d);
                s1 += __shfl_xor_sync(0xFFFFFFFFu, s1, d);
                t0 += __shfl_xor_sync(0xFFFFFFFFu, t0, d);
                t1 += __shfl_xor_sync(0xFFFFFFFFu, t1, d);
            }
            if (r == 0) {
                pS[wid * NTILE + c0c]     = s0;
                pS[wid * NTILE + c0c + 1] = s1;
                pQ[wid * NTILE + c0c]     = t0;
                pQ[wid * NTILE + c0c + 1] = t1;
            }
        }
    } else {
        int cp = (lane & 3) << 1;
        bool writer = ((lane >> 2) & 3) == 0;
        int gsel = lane >> 4;
        int qout0 = blockIdx.x * 32 + wid * 4;
#pragma unroll
        for (int nt = 0; nt < NT; nt++) {
            float v0 = acc[nt][0], v1 = acc[nt][1];
            float v2 = acc[nt][2], v3 = acc[nt][3];
            if (bias) {
                float b0 = bias[o0 + nt * 8 + cp];
                float b1v = bias[o0 + nt * 8 + cp + 1];
                v0 += b0; v2 += b0; v1 += b1v; v3 += b1v;
            }
#pragma unroll
            for (int d = 4; d <= 8; d <<= 1) {
                v0 = fmaxf(v0, __shfl_xor_sync(0xFFFFFFFFu, v0, d));
                v1 = fmaxf(v1, __shfl_xor_sync(0xFFFFFFFFu, v1, d));
                v2 = fmaxf(v2, __shfl_xor_sync(0xFFFFFFFFu, v2, d));
                v3 = fmaxf(v3, __shfl_xor_sync(0xFFFFFFFFu, v3, d));
            }
            if (writer) {
                int oc0 = o0 + nt * 8 + cp;
                bool inU = (oc0 < OSPLIT);
                int oc = inU ? oc0 : (oc0 - OSPLIT);
                float* outp = inU ? outU : outV;
                int stride = inU ? CU : CV;
                int qa = qout0 + gsel;
                int qb2 = qout0 + 2 + gsel;
                outp[(size_t)qa * stride + oc]      = v0;
                outp[(size_t)qa * stride + oc + 1]  = v1;
                outp[(size_t)qb2 * stride + oc]     = v2;
                outp[(size_t)qb2 * stride + oc + 1] = v3;
            }
            float s0 = v0 + v2, s1 = v1 + v3;
            float t0 = v0 * v0 + v2 * v2, t1 = v1 * v1 + v3 * v3;
            s0 += __shfl_xor_sync(0xFFFFFFFFu, s0, 16);
            s1 += __shfl_xor_sync(0xFFFFFFFFu, s1, 16);
            t0 += __shfl_xor_sync(0xFFFFFFFFu, t0, 16);
            t1 += __shfl_xor_sync(0xFFFFFFFFu, t1, 16);
            if (lane < 4) {
                pS[wid * NTILE + nt * 8 + cp]     = s0;
                pS[wid * NTILE + nt * 8 + cp + 1] = s1;
                pQ[wid * NTILE + nt * 8 + cp]     = t0;
                pQ[wid * NTILE + nt * 8 + cp + 1] = t1;
            }
        }
    }
    __syncthreads();
    if (tid < NTILE) {
        float s = 0.f, q = 0.f;
#pragma unroll
        for (int w = 0; w < 8; w++) { s += pS[w * NTILE + tid]; q += pQ[w * NTILE + tid]; }
        psum[(size_t)blockIdx.x * NSTR + o0 + tid] = s;
        psq [(size_t)blockIdx.x * NSTR + o0 + tid] = q;
    }
}

// ------- final: BN+add+relu, global max (position-major inputs) -------------
__global__ __launch_bounds__(256) void maxfinP_k(
    const float* __restrict__ w2, const float* __restrict__ v2,
    const float* __restrict__ scC, const float* __restrict__ shC,
    const float* __restrict__ scD, const float* __restrict__ shD,
    float* __restrict__ gmax) {
    int b = blockIdx.x, o = threadIdx.x;
    float a = scC[o], c_ = shC[o], d = scD[o], e = shD[o];
    float mx = 0.f;
#pragma unroll 1
    for (int f = 0; f < 5; f++) {
        size_t rowbase = ((size_t)(f * 256 + b) * 32) * 256 + o;
#pragma unroll
        for (int i = 0; i < 32; i++) {
            size_t idx = rowbase + (size_t)i * 256;
            float val = a * w2[idx] + c_ + d * v2[idx] + e;
            mx = fmaxf(mx, fmaxf(val, 0.f));
        }
    }
    gmax[b * 256 + o] = mx;
}

__global__ void fc_k(const float* __restrict__ gmax, const float* __restrict__ fw,
                     const float* __restrict__ fb, float* __restrict__ out) {
    int b = blockIdx.x, tid = threadIdx.x;
    __shared__ float m[256];
    m[tid] = gmax[b * 256 + tid];
    __syncthreads();
    if (tid < 10) {
        float acc = fb[tid];
        for (int o = 0; o < 256; o++) acc += m[o] * fw[tid * 256 + o];
        out[b * 10 + tid] = acc;
    }
}

// ------------------------- launch ------------------------------------------
#define SMK16V 36608
#define SM64V  64000
#define SMENT  86528
#define SM256V 89600

extern "C" void kernel_launch(void* const* d_in, const int* in_sizes, int n_in,
                              void* d_out, int out_size) {
    (void)n_in; (void)out_size;

    const float* x = (const float*)d_in[0];

    float *u1,*v1,*h1,*w1,*u2,*v2,*h2,*w2,*gmax,*ps,*pq,*sc,*sh,*bias2;
    __nv_bfloat16 *whex_hi,*whex_lo,*wb1h_hi,*wb1h_lo,*went_hi,*went_lo;
    __nv_bfloat16 *wc3_hi,*wc3_lo,*wb1c3_hi,*wb1c3_lo,*went2_hi,*went2_lo;
    __nv_bfloat16 *ahi,*alo;
    cudaGetSymbolAddress((void**)&u1, g_u1);
    cudaGetSymbolAddress((void**)&v1, g_v1);
    cudaGetSymbolAddress((void**)&h1, g_h1);
    cudaGetSymbolAddress((void**)&w1, g_w1);
    cudaGetSymbolAddress((void**)&u2, g_u2);
    cudaGetSymbolAddress((void**)&v2, g_v2);
    cudaGetSymbolAddress((void**)&h2, g_h2);
    cudaGetSymbolAddress((void**)&w2, g_w2);
    cudaGetSymbolAddress((void**)&gmax, g_gmax);
    cudaGetSymbolAddress((void**)&ps, g_psum);
    cudaGetSymbolAddress((void**)&pq, g_psq);
    cudaGetSymbolAddress((void**)&sc, g_scale);
    cudaGetSymbolAddress((void**)&sh, g_shift);
    cudaGetSymbolAddress((void**)&bias2, g_bias2);
    cudaGetSymbolAddress((void**)&whex_hi, g_whex_hi);
    cudaGetSymbolAddress((void**)&whex_lo, g_whex_lo);
    cudaGetSymbolAddress((void**)&wb1h_hi, g_wb1h_hi);
    cudaGetSymbolAddress((void**)&wb1h_lo, g_wb1h_lo);
    cudaGetSymbolAddress((void**)&went_hi, g_went_hi);
    cudaGetSymbolAddress((void**)&went_lo, g_went_lo);
    cudaGetSymbolAddress((void**)&wc3_hi, g_wc3_hi);
    cudaGetSymbolAddress((void**)&wc3_lo, g_wc3_lo);
    cudaGetSymbolAddress((void**)&wb1c3_hi, g_wb1c3_hi);
    cudaGetSymbolAddress((void**)&wb1c3_lo, g_wb1c3_lo);
    cudaGetSymbolAddress((void**)&went2_hi, g_went2_hi);
    cudaGetSymbolAddress((void**)&went2_lo, g_went2_lo);
    cudaGetSymbolAddress((void**)&ahi, g_abf_hi);
    cudaGetSymbolAddress((void**)&alo, g_abf_lo);

    // input index tables (runtime disambiguation of metadata order)
    int I_b1c1, I_b1hex, I_b1c3, I_b1ds;
    int I_b1ga, I_b1ba, I_b1gb, I_b1bb, I_b1gc, I_b1bc, I_b1gd, I_b1bd;
    int I_b2c1, I_b2hex, I_b2c3, I_b2ds;
    int I_b2ga, I_b2ba, I_b2gb, I_b2bb, I_b2gc, I_b2bc, I_b2gd, I_b2bd;
    int I_fcw, I_fcb;
    if (in_sizes[5] == 36864) {
        I_b1c1 = 4;  I_b1hex = 5;  I_b1c3 = 6;  I_b1ds = 7;
        I_b1ga = 8;  I_b1ba = 9;  I_b1gb = 10; I_b1bb = 11;
        I_b1gc = 12; I_b1bc = 13; I_b1gd = 14; I_b1bd = 15;
        I_b2c1 = 16; I_b2hex = 17; I_b2c3 = 18; I_b2ds = 19;
        I_b2ga = 20; I_b2ba = 21; I_b2gb = 22; I_b2bb = 23;
        I_b2gc = 24; I_b2bc = 25; I_b2gd = 26; I_b2bd = 27;
        I_fcw = 28;  I_fcb = 29;
    } else {
        I_b1c1 = 4;  I_b1ga = 5;  I_b1ba = 6;  I_b1hex = 7;
        I_b1gb = 8;  I_b1bb = 9;  I_b1c3 = 10; I_b1gc = 11; I_b1bc = 12;
        I_b1ds = 13; I_b1gd = 14; I_b1bd = 15;
        I_b2c1 = 16; I_b2ga = 17; I_b2ba = 18; I_b2hex = 19;
        I_b2gb = 20; I_b2bb = 21; I_b2c3 = 22; I_b2gc = 23; I_b2bc = 24;
        I_b2ds = 25; I_b2gd = 26; I_b2bd = 27;
        I_fcw = 28;  I_fcb = 29;
    }

    // set smem limits for mma instantiations
    cudaFuncSetAttribute(mma_conv_k<16, 128, 1, true, 16, 32, 128, 64, 16, 64, 64, 0>,
                         cudaFuncAttributeMaxDynamicSharedMemorySize, SMK16V);
    cudaFuncSetAttribute(mma_conv_k<512, 64, 7, false, 8, 16, 64, 64, 64, 64, 1, 1>,
                         cudaFuncAttributeMaxDynamicSharedMemorySize, SM64V);
    cudaFuncSetAttribute(mma_conv_k<64, 64, 1, false, 8, 16, 64, 64, 64, 64, 1, 1>,
                         cudaFuncAttributeMaxDynamicSharedMemorySize, SM64V);
    cudaFuncSetAttribute(mma_conv_k<64, 128, 1, true, 8, 16, 512, 256, 64, 256, 256, 2>,
                         cudaFuncAttributeMaxDynamicSharedMemorySize, SMENT);
    cudaFuncSetAttribute(mma_conv_k<2048, 128, 7, false, 4, 8, 256, 256, 256, 256, 1, 1>,
                         cudaFuncAttributeMaxDynamicSharedMemorySize, SM256V);
    cudaFuncSetAttribute(mma_conv_k<256, 128, 1, false, 4, 8, 256, 256, 256, 256, 1, 1>,
                         cudaFuncAttributeMaxDynamicSharedMemorySize, SM256V);

    // weight prep
    hexsplit_k<<<2048, 256>>>((const float*)d_in[I_b2hex], whex_hi, whex_lo, 256, 256);
    hexsplit_k<<<128,  256>>>((const float*)d_in[I_b1hex], wb1h_hi, wb1h_lo, 64, 64);
    split1x1_k<<<64,  256>>>((const float*)d_in[I_b2c1], went_hi, went_lo, 256, 64, 0);
    split1x1_k<<<64,  256>>>((const float*)d_in[I_b2ds], went_hi, went_lo, 256, 64, 256);
    split1x1_k<<<256, 256>>>((const float*)d_in[I_b2c3], wc3_hi, wc3_lo, 256, 256, 0);
    split1x1_k<<<16,  256>>>((const float*)d_in[I_b1c3], wb1c3_hi, wb1c3_lo, 64, 64, 0);

    // stem: hexconv -> relu -> bf16 planes [pos][16] + bn1 stats
    stem_kernel<<<NP0 / 256, 256>>>(x, (const float*)d_in[1], ahi, alo, ps, pq);
    bn_param<<<16, 256>>>(ps, pq, NP0 / 256, 16, 0, 1.f / NP0,
                          (const float*)d_in[2], (const float*)d_in[3], sc + 0, sh + 0);
    foldentry_k<<<1, 128>>>((const float*)d_in[I_b1c1], (const float*)d_in[I_b1ds],
                            sc + 0, sh + 0, went2_hi, went2_lo, bias2);

    // block1 entry (mma, K=16, pooled, bias, N=128 = main||ds)
    mma_conv_k<16, 128, 1, true, 16, 32, 128, 64, 16, 64, 64, 0>
        <<<dim3(NP0 / 128, 1), 256, SMK16V>>>(
            ahi, alo, nullptr, nullptr, nullptr, nullptr, nullptr, nullptr,
            went2_hi, went2_lo, bias2, u1, v1, ps, pq);
    bn_param<<<64, 256>>>(ps, pq, NP0 / 128, 128, 0,  1.f / NP1,
                          (const float*)d_in[I_b1ga], (const float*)d_in[I_b1ba], sc + 16,  sh + 16);
    bn_param<<<64, 256>>>(ps, pq, NP0 / 128, 128, 64, 1.f / NP1,
                          (const float*)d_in[I_b1gd], (const float*)d_in[I_b1bd], sc + 208, sh + 208);

    // block1 hexconv (mma, fused affine from u1)
    mma_conv_k<512, 64, 7, false, 8, 16, 64, 64, 64, 64, 1, 1>
        <<<dim3(NP1 / 128, 1), 256, SM64V>>>(
            nullptr, nullptr, u1, nullptr, sc + 16, sh + 16, nullptr, nullptr,
            wb1h_hi, wb1h_lo, nullptr, h1, nullptr, ps, pq);
    bn_param<<<64, 256>>>(ps, pq, NP1 / 128, 64, 0, 1.f / NP1,
                          (const float*)d_in[I_b1gb], (const float*)d_in[I_b1bb], sc + 80, sh + 80);

    // block1 conv3 1x1 (mma, fused affine from h1)
    mma_conv_k<64, 64, 1, false, 8, 16, 64, 64, 64, 64, 1, 1>
        <<<dim3(NP1 / 128, 1), 256, SM64V>>>(
            nullptr, nullptr, h1, nullptr, sc + 80, sh + 80, nullptr, nullptr,
            wb1c3_hi, wb1c3_lo, nullptr, w1, nullptr, ps, pq);
    bn_param<<<64, 256>>>(ps, pq, NP1 / 128, 64, 0, 1.f / NP1,
                          (const float*)d_in[I_b1gc], (const float*)d_in[I_b1bc], sc + 144, sh + 144);

    // block2 entry (mma, dual fused affine from w1+v1, pooled, N=512)
    mma_conv_k<64, 128, 1, true, 8, 16, 512, 256, 64, 256, 256, 2>
        <<<dim3(NP1 / 128, 4), 256, SMENT>>>(
            nullptr, nullptr, w1, v1, sc + 144, sh + 144, sc + 208, sh + 208,
            went_hi, went_lo, nullptr, u2, v2, ps, pq);
    bn_param<<<256, 256>>>(ps, pq, NP1 / 128, 512, 0,   1.f / NP2,
                           (const float*)d_in[I_b2ga], (const float*)d_in[I_b2ba], sc + 272,  sh + 272);
    bn_param<<<256, 256>>>(ps, pq, NP1 / 128, 512, 256, 1.f / NP2,
                           (const float*)d_in[I_b2gd], (const float*)d_in[I_b2bd], sc + 1040, sh + 1040);

    // block2 hexconv (mma, fused affine from u2)
    mma_conv_k<2048, 128, 7, false, 4, 8, 256, 256, 256, 256, 1, 1>
        <<<dim3(NP2 / 128, 2), 256, SM256V>>>(
            nullptr, nullptr, u2, nullptr, sc + 272, sh + 272, nullptr, nullptr,
            whex_hi, whex_lo, nullptr, h2, nullptr, ps, pq);
    bn_param<<<256, 256>>>(ps, pq, NP2 / 128, 256, 0, 1.f / NP2,
                           (const float*)d_in[I_b2gb], (const float*)d_in[I_b2bb], sc + 528, sh + 528);

    // block2 conv3 1x1 (mma, fused affine from h2)
    mma_conv_k<256, 128, 1, false, 4, 8, 256, 256, 256, 256, 1, 1>
        <<<dim3(NP2 / 128, 2), 256, SM256V>>>(
            nullptr, nullptr, h2, nullptr, sc + 528, sh + 528, nullptr, nullptr,
            wc3_hi, wc3_lo, nullptr, w2, nullptr, ps, pq);
    bn_param<<<256, 256>>>(ps, pq, NP2 / 128, 256, 0, 1.f / NP2,
                           (const float*)d_in[I_b2gc], (const float*)d_in[I_b2bc], sc + 784, sh + 784);

    // tail
    maxfinP_k<<<256, 256>>>(w2, v2, sc + 784, sh + 784, sc + 1040, sh + 1040, gmax);
    fc_k<<<256, 256>>>(gmax, (const float*)d_in[I_fcw], (const float*)d_in[I_fcb], (float*)d_out);
}

// round 15
// speedup vs baseline: 1.1277x; 1.1277x over previous
#include <cuda_runtime.h>
#include <cuda_bf16.h>
#include <cstdint>

// Geometry:
//  stage0 in : [5][256][3][16][32]
//  stem out  : 16ch @16x32, NP0 = 5*256*512 = 655360
//  block1    : 64ch @8x16,  NP1 = 5*256*128 = 163840
//  block2    : 256ch@4x8,   NP2 = 5*256*32  = 40960
// ALL activations position-major: fp32 t[pos*C + c]; bf16 planes [pos][C]

#define NP0 655360
#define NP1 163840
#define NP2 40960

// ------------------------- device scratch ----------------------------------
__device__ float g_u1[64 * NP1];
__device__ float g_v1[64 * NP1];
__device__ float g_h1[64 * NP1];
__device__ float g_w1[64 * NP1];
__device__ float g_u2[256 * NP2];
__device__ float g_v2[256 * NP2];
__device__ float g_h2[256 * NP2];
__device__ float g_w2[256 * NP2];
__device__ float g_gmax[256 * 256];

__device__ float g_psum[1310720];
__device__ float g_psq [1310720];

__device__ float g_scale[1296];
__device__ float g_shift[1296];

// split bf16 weights (hex: k = chunk*64 + t*8 + cl, tap7 = 0)
__device__ __nv_bfloat16 g_whex_hi[256 * 2048];
__device__ __nv_bfloat16 g_whex_lo[256 * 2048];
__device__ __nv_bfloat16 g_wb1h_hi[64 * 512];
__device__ __nv_bfloat16 g_wb1h_lo[64 * 512];
__device__ __nv_bfloat16 g_went_hi[512 * 64];
__device__ __nv_bfloat16 g_went_lo[512 * 64];
__device__ __nv_bfloat16 g_wc3_hi [256 * 256];
__device__ __nv_bfloat16 g_wc3_lo [256 * 256];
__device__ __nv_bfloat16 g_wb1c3_hi[64 * 64];
__device__ __nv_bfloat16 g_wb1c3_lo[64 * 64];
// block1 entry: folded (bn1-scaled) weights [128 o][16 c] + bias
__device__ __nv_bfloat16 g_went2_hi[128 * 16];
__device__ __nv_bfloat16 g_went2_lo[128 * 16];
__device__ float g_bias2[128];

// bf16 activation planes [pos][C] (stem / hex inputs; reused sequentially)
__device__ __nv_bfloat16 g_abf_hi[10485760];
__device__ __nv_bfloat16 g_abf_lo[10485760];

// ------------------------- mma helpers -------------------------------------
__device__ __forceinline__ uint32_t smem_u32(const void* p) {
    uint32_t a;
    asm("{ .reg .u64 t; cvta.to.shared.u64 t, %1; cvt.u32.u64 %0, t; }"
        : "=r"(a) : "l"(p));
    return a;
}
__device__ __forceinline__ void ldmA(uint32_t* a, uint32_t addr) {
    asm volatile("ldmatrix.sync.aligned.m8n8.x4.shared.b16 {%0,%1,%2,%3}, [%4];"
        : "=r"(a[0]), "=r"(a[1]), "=r"(a[2]), "=r"(a[3]) : "r"(addr));
}
__device__ __forceinline__ void ldmB(uint32_t* b, uint32_t addr) {
    asm volatile("ldmatrix.sync.aligned.m8n8.x2.shared.b16 {%0,%1}, [%2];"
        : "=r"(b[0]), "=r"(b[1]) : "r"(addr));
}
__device__ __forceinline__ void mma16816(float* d, const uint32_t* a, const uint32_t* b) {
    asm volatile(
        "mma.sync.aligned.m16n8k16.row.col.f32.bf16.bf16.f32 "
        "{%0,%1,%2,%3}, {%4,%5,%6,%7}, {%8,%9}, {%0,%1,%2,%3};"
        : "+f"(d[0]), "+f"(d[1]), "+f"(d[2]), "+f"(d[3])
        : "r"(a[0]), "r"(a[1]), "r"(a[2]), "r"(a[3]), "r"(b[0]), "r"(b[1]));
}

// ------------------------- prep kernels ------------------------------------
__global__ void hexsplit_k(const float* __restrict__ src,
                           __nv_bfloat16* __restrict__ hi, __nv_bfloat16* __restrict__ lo,
                           int O, int C) {
    int i = blockIdx.x * 256 + threadIdx.x;
    if (i < O * C * 8) {
        int t = i & 7;
        int c = (i >> 3) % C;
        int o = i / (8 * C);
        float w = (t < 7) ? src[(o * C + c) * 9 + t + 1] : 0.f;
        __nv_bfloat16 h = __float2bfloat16(w);
        int k = (c >> 3) * 64 + t * 8 + (c & 7);
        hi[(size_t)o * (C * 8) + k] = h;
        lo[(size_t)o * (C * 8) + k] = __float2bfloat16(w - __bfloat162float(h));
    }
}

__global__ void split1x1_k(const float* __restrict__ src,
                           __nv_bfloat16* __restrict__ hi, __nv_bfloat16* __restrict__ lo,
                           int O, int C, int rowoff) {
    int i = blockIdx.x * 256 + threadIdx.x;
    if (i < O * C) {
        float w = src[i];
        __nv_bfloat16 h = __float2bfloat16(w);
        int o = i / C, c = i % C;
        hi[(rowoff + o) * C + c] = h;
        lo[(rowoff + o) * C + c] = __float2bfloat16(w - __bfloat162float(h));
    }
}

// fold bn1 affine into block1-entry weights: w' = w*s_c, bias = sum w*t_c
__global__ void foldentry_k(const float* __restrict__ c1w, const float* __restrict__ dsw,
                            const float* __restrict__ sc0, const float* __restrict__ sh0,
                            __nv_bfloat16* __restrict__ hi, __nv_bfloat16* __restrict__ lo,
                            float* __restrict__ bias) {
    int o = threadIdx.x;  // 128
    const float* src = (o < 64) ? (c1w + o * 16) : (dsw + (o - 64) * 16);
    float b = 0.f;
    for (int c = 0; c < 16; c++) {
        float w = src[c] * sc0[c];
        b += src[c] * sh0[c];
        __nv_bfloat16 h = __float2bfloat16(w);
        hi[o * 16 + c] = h;
        lo[o * 16 + c] = __float2bfloat16(w - __bfloat162float(h));
    }
    bias[o] = b;
}

// relu(sc*x+sh), position-major fp32 [pos][C] -> bf16 hi/lo [pos][C]
__global__ __launch_bounds__(256) void actsplitP_k(
    const float* __restrict__ x, const float* __restrict__ sc,
    const float* __restrict__ sh,
    __nv_bfloat16* __restrict__ hi, __nv_bfloat16* __restrict__ lo, int C) {
    size_t i = (size_t)blockIdx.x * 256 + threadIdx.x;   // quad index
    float4 v4 = *(const float4*)(x + i * 4);
    int c0 = (int)((i * 4) % C);
    float v[4] = {v4.x, v4.y, v4.z, v4.w};
    __align__(8) __nv_bfloat16 h4[4], l4[4];
#pragma unroll
    for (int j = 0; j < 4; j++) {
        float vv = fmaxf(sc[c0 + j] * v[j] + sh[c0 + j], 0.f);
        __nv_bfloat16 hb = __float2bfloat16(vv);
        h4[j] = hb;
        l4[j] = __float2bfloat16(vv - __bfloat162float(hb));
    }
    *(uint2*)(hi + i * 4) = *(uint2*)h4;
    *(uint2*)(lo + i * 4) = *(uint2*)l4;
}

// ------------------------- stem: hexconv -> relu -> bf16 planes -------------
__global__ __launch_bounds__(256) void stem_kernel(
    const float* __restrict__ x, const float* __restrict__ wc,
    __nv_bfloat16* __restrict__ ahi, __nv_bfloat16* __restrict__ alo,
    float* __restrict__ psum, float* __restrict__ psq) {
    __shared__ float wsh[432];
    __shared__ float wpS[16][8], wpQ[16][8];
    int tid = threadIdx.x;
    for (int e = tid; e < 432; e += 256) wsh[e] = wc[e];
    __syncthreads();

    int pos = blockIdx.x * 256 + tid;
    int w = pos & 31, h = (pos >> 5) & 15, b = (pos >> 9) & 255, f = pos >> 17;

    float acc[16];
#pragma unroll
    for (int o = 0; o < 16; o++) acc[o] = 0.f;

#pragma unroll
    for (int t = 0; t < 7; t++) {
        int kf = t + 1;
        int dy = kf / 3 - 1, dx = kf % 3 - 1;
        int hh = h + dy;
        float xv0 = 0.f, xv1 = 0.f, xv2 = 0.f;
        if (hh >= 0 && hh < 16) {
            int ww = w + dx, ff = f;
            if (ww < 0)       { ff = (f + 4) % 5; ww = 31; }
            else if (ww > 31) { ff = (f + 1) % 5; ww = 0;  }
            int base = (ff * 256 + b) * 1536 + hh * 32 + ww;
            xv0 = x[base];
            xv1 = x[base + 512];
            xv2 = x[base + 1024];
        }
#pragma unroll
        for (int o = 0; o < 16; o++) {
            acc[o] += wsh[(o * 3 + 0) * 9 + kf] * xv0
                    + wsh[(o * 3 + 1) * 9 + kf] * xv1
                    + wsh[(o * 3 + 2) * 9 + kf] * xv2;
        }
    }

    __align__(16) __nv_bfloat16 h16[16];
    __align__(16) __nv_bfloat16 l16[16];
    int lane = tid & 31, warp = tid >> 5;
#pragma unroll
    for (int o = 0; o < 16; o++) {
        float val = fmaxf(acc[o], 0.f);
        __nv_bfloat16 hb = __float2bfloat16(val);
        h16[o] = hb;
        l16[o] = __float2bfloat16(val - __bfloat162float(hb));
        float s = val, q2 = val * val;
#pragma unroll
        for (int d = 16; d; d >>= 1) {
            s  += __shfl_xor_sync(0xFFFFFFFFu, s,  d);
            q2 += __shfl_xor_sync(0xFFFFFFFFu, q2, d);
        }
        if (lane == 0) { wpS[o][warp] = s; wpQ[o][warp] = q2; }
    }
    *(uint4*)(ahi + (size_t)pos * 16)     = *(uint4*)h16;
    *(uint4*)(ahi + (size_t)pos * 16 + 8) = *(uint4*)(h16 + 8);
    *(uint4*)(alo + (size_t)pos * 16)     = *(uint4*)l16;
    *(uint4*)(alo + (size_t)pos * 16 + 8) = *(uint4*)(l16 + 8);

    __syncthreads();
    if (tid < 16) {
        float s = 0.f, q = 0.f;
#pragma unroll
        for (int wpi = 0; wpi < 8; wpi++) { s += wpS[tid][wpi]; q += wpQ[tid][wpi]; }
        psum[blockIdx.x * 16 + tid] = s;
        psq [blockIdx.x * 16 + tid] = q;
    }
}

// ------------------------- BN param fold ------------------------------------
__global__ void bn_param(const float* __restrict__ ps, const float* __restrict__ pq,
                         int nparts, int cstride, int coff, float invN,
                         const float* __restrict__ g, const float* __restrict__ b,
                         float* __restrict__ sc, float* __restrict__ sh) {
    int c = blockIdx.x, tid = threadIdx.x;
    float s = 0.f, q = 0.f;
    for (int p = tid; p < nparts; p += 256) {
        s += ps[(size_t)p * cstride + coff + c];
        q += pq[(size_t)p * cstride + coff + c];
    }
    __shared__ float rs[256], rq[256];
    rs[tid] = s; rq[tid] = q;
    __syncthreads();
    for (int d = 128; d; d >>= 1) {
        if (tid < d) { rs[tid] += rs[tid + d]; rq[tid] += rq[tid + d]; }
        __syncthreads();
    }
    if (tid == 0) {
        float mean = rs[0] * invN;
        float var  = rq[0] * invN - mean * mean;
        float k = g[c] * rsqrtf(var + 1e-5f);
        sc[c] = k;
        sh[c] = b[c] - mean * k;
    }
}

// ---------------- generic mma.sync split-bf16 conv/GEMM ---------------------
// D[m=128, o=NTILE] = A[m, k] * W[o, k].
// AMODE 0: A from bf16 planes ahi/alo [pos][CDIM].
// AMODE 1: A = relu(scA*xf1+shA) fused at staging (fp32 [pos][CDIM]).
// AMODE 2: A = relu(scA*xf1+shA + scB*xf2+shB).
// Outputs POSITION-MAJOR fp32: oc<OSPLIT -> outU[q*CU+oc] else outV[q*CV+oc-OSPLIT].
template <int KTOT, int NTILE, int TAPS, bool POOL, int HIN, int WIN,
          int NSTR, int OSPLIT, int CDIM, int CU, int CV, int AMODE>
__global__ __launch_bounds__(256) void mma_conv_k(
    const __nv_bfloat16* __restrict__ ahi, const __nv_bfloat16* __restrict__ alo,
    const float* __restrict__ xf1, const float* __restrict__ xf2,
    const float* __restrict__ scA, const float* __restrict__ shA,
    const float* __restrict__ scB, const float* __restrict__ shB,
    const __nv_bfloat16* __restrict__ whi, const __nv_bfloat16* __restrict__ wlo,
    const float* __restrict__ bias,
    float* __restrict__ outU, float* __restrict__ outV,
    float* __restrict__ psum, float* __restrict__ psq) {
    constexpr int NT = NTILE / 8;
    constexpr int KCH = (KTOT < 64) ? KTOT : 64;
    constexpr int NCHUNK = KTOT / KCH;
    constexpr int LDAv = KCH + 8;
    constexpr int GPR = KCH / 8;
    constexpr int KS = KCH / 16;
    constexpr int AITERS = (128 * GPR) / 256;
    constexpr int BITERS = (NTILE * GPR + 255) / 256;
    constexpr int OF_SC = 3584;
    constexpr int OF_AH = OF_SC + 4 * CDIM * 4;
    constexpr int OF_AL = OF_AH + 128 * LDAv * 2;
    constexpr int OF_BH = OF_AL + 128 * LDAv * 2;
    constexpr int OF_BL = OF_BH + NTILE * LDAv * 2;
    constexpr int OF_PS = OF_BL + NTILE * LDAv * 2;
    constexpr int OF_PQ = OF_PS + NTILE * 32;

    extern __shared__ __align__(16) char smem[];
    uint32_t sb = smem_u32(smem);
    int tid = threadIdx.x;
    int wid = tid >> 5, lane = tid & 31;
    int q0 = blockIdx.x * 128;
    int o0 = blockIdx.y * NTILE;

    int* nbr = (int*)(smem);
    for (int e = tid; e < TAPS * 128; e += 256) {
        int t = e >> 7, ql = e & 127;
        int m = q0 + ql;
        int pos;
        if (POOL) {
            constexpr int WO = WIN / 2, HO = HIN / 2;
            int qq = m >> 2, sub = m & 3;
            int w = qq % WO;
            int h = (qq / WO) % HO;
            int fb = qq / (WO * HO);
            pos = (fb * HIN + 2 * h + (sub >> 1)) * WIN + 2 * w + (sub & 1);
        } else if (TAPS == 1) {
            pos = m;
        } else {
            int w = m % WIN;
            int h = (m / WIN) % HIN;
            int b = (m / (WIN * HIN)) & 255;
            int f = m / (WIN * HIN * 256);
            int kf = t + 1;
            int dy = kf / 3 - 1, dx = kf % 3 - 1;
            int hh = h + dy, ww = w + dx, ff = f;
            if (hh < 0 || hh >= HIN) pos = -1;
            else {
                if (ww < 0)        { ff = (f + 4) % 5; ww = WIN - 1; }
                else if (ww >= WIN){ ff = (f + 1) % 5; ww = 0;       }
                pos = ((ff * 256 + b) * HIN + hh) * WIN + ww;
            }
        }
        nbr[t * 128 + ql] = pos;
    }
    float* scS  = (float*)(smem + OF_SC);
    float* shS  = scS + CDIM;
    float* sc2S = shS + CDIM;
    float* sh2S = sc2S + CDIM;
    if (AMODE >= 1) {
        for (int c = tid; c < CDIM; c += 256) {
            scS[c] = scA[c];
            shS[c] = shA[c];
            if (AMODE == 2) { sc2S[c] = scB[c]; sh2S[c] = shB[c]; }
        }
    }
    __syncthreads();

    float acc[NT][4];
#pragma unroll
    for (int nt = 0; nt < NT; nt++)
#pragma unroll
        for (int j = 0; j < 4; j++) acc[nt][j] = 0.f;

    int m0 = wid * 16;
    int grp = lane >> 3;
    int rowA = m0 + (lane & 7) + (grp & 1) * 8;
    int colA8 = (grp >> 1) * 8;
    uint32_t aBaseH = sb + OF_AH + (uint32_t)(rowA * LDAv + colA8) * 2;
    uint32_t aBaseL = sb + OF_AL + (uint32_t)(rowA * LDAv + colA8) * 2;
    int rowB = (lane & 7);
    int colB8 = ((lane >> 3) & 1) * 8;
    uint32_t bBaseH = sb + OF_BH + (uint32_t)(rowB * LDAv + colB8) * 2;
    uint32_t bBaseL = sb + OF_BL + (uint32_t)(rowB * LDAv + colB8) * 2;

    __nv_bfloat16* AH = (__nv_bfloat16*)(smem + OF_AH);
    __nv_bfloat16* AL = (__nv_bfloat16*)(smem + OF_AL);
    __nv_bfloat16* BH = (__nv_bfloat16*)(smem + OF_BH);
    __nv_bfloat16* BL = (__nv_bfloat16*)(smem + OF_BL);

#pragma unroll 1
    for (int ci = 0; ci < NCHUNK; ci++) {
        // stage A: [128 m][KCH k]
#pragma unroll
        for (int it = 0; it < AITERS; it++) {
            int e = it * 256 + tid;
            int q = e / GPR, g = e % GPR;
            int pos = -1, c0;
            if (TAPS == 7) { c0 = ci * 8; if (g < 7) pos = nbr[g * 128 + q]; }
            else           { c0 = ci * KCH + g * 8; pos = nbr[q]; }
            if (AMODE == 0) {
                uint4 vh = {0u, 0u, 0u, 0u}, vl = {0u, 0u, 0u, 0u};
                if (pos >= 0) {
                    size_t base = (size_t)pos * CDIM + c0;
                    vh = *(const uint4*)(ahi + base);
                    vl = *(const uint4*)(alo + base);
                }
                *(uint4*)(AH + q * LDAv + g * 8) = vh;
                *(uint4*)(AL + q * LDAv + g * 8) = vl;
            } else {
                float v[8] = {0.f, 0.f, 0.f, 0.f, 0.f, 0.f, 0.f, 0.f};
                if (pos >= 0) {
                    const float* p1 = xf1 + (size_t)pos * CDIM + c0;
                    float4 f0 = *(const float4*)p1;
                    float4 f1 = *(const float4*)(p1 + 4);
                    float r1[8] = {f0.x, f0.y, f0.z, f0.w, f1.x, f1.y, f1.z, f1.w};
                    if (AMODE == 2) {
                        const float* p2 = xf2 + (size_t)pos * CDIM + c0;
                        float4 g0 = *(const float4*)p2;
                        float4 g1 = *(const float4*)(p2 + 4);
                        float r2[8] = {g0.x, g0.y, g0.z, g0.w, g1.x, g1.y, g1.z, g1.w};
#pragma unroll
                        for (int j = 0; j < 8; j++)
                            v[j] = fmaxf(scS[c0 + j] * r1[j] + shS[c0 + j]
                                       + sc2S[c0 + j] * r2[j] + sh2S[c0 + j], 0.f);
                    } else {
#pragma unroll
                        for (int j = 0; j < 8; j++)
                            v[j] = fmaxf(scS[c0 + j] * r1[j] + shS[c0 + j], 0.f);
                    }
                }
                __align__(16) __nv_bfloat16 h8[8], l8[8];
#pragma unroll
                for (int j = 0; j < 8; j++) {
                    __nv_bfloat16 hb = __float2bfloat16(v[j]);
                    h8[j] = hb;
                    l8[j] = __float2bfloat16(v[j] - __bfloat162float(hb));
                }
                *(uint4*)(AH + q * LDAv + g * 8) = *(uint4*)h8;
                *(uint4*)(AL + q * LDAv + g * 8) = *(uint4*)l8;
            }
        }
        // stage B: [NTILE o][KCH k]
#pragma unroll
        for (int it = 0; it < BITERS; it++) {
            int e = it * 256 + tid;
            if (e < NTILE * GPR) {
                int o = e / GPR, j = e % GPR;
                size_t src = (size_t)(o0 + o) * KTOT + ci * KCH + j * 8;
                *(uint4*)(BH + o * LDAv + j * 8) = *(const uint4*)(whi + src);
                *(uint4*)(BL + o * LDAv + j * 8) = *(const uint4*)(wlo + src);
            }
        }
        __syncthreads();

#pragma unroll
        for (int ks = 0; ks < KS; ks++) {
            uint32_t aH[4], aL[4];
            ldmA(aH, aBaseH + ks * 32);
            ldmA(aL, aBaseL + ks * 32);
#pragma unroll
            for (int nt = 0; nt < NT; nt++) {
                uint32_t bH[2], bL[2];
                uint32_t boff = (uint32_t)(nt * 8 * LDAv) * 2 + ks * 32;
                ldmB(bH, bBaseH + boff);
                ldmB(bL, bBaseL + boff);
                mma16816(acc[nt], aH, bH);
                mma16816(acc[nt], aL, bH);
                mma16816(acc[nt], aH, bL);
            }
        }
        __syncthreads();
    }

    float* pS = (float*)(smem + OF_PS);
    float* pQ = (float*)(smem + OF_PQ);

    if (!POOL) {
        int r = lane >> 2;
        int cp = (lane & 3) << 1;
#pragma unroll
        for (int nt = 0; nt < NT; nt++) {
            int c0c = nt * 8 + cp;
            int qrow = q0 + m0 + r;
            int oc0 = o0 + c0c;
            bool inU = (oc0 < OSPLIT);
            float* base = inU ? (outU + (size_t)qrow * CU + oc0)
                              : (outV + (size_t)qrow * CV + (oc0 - OSPLIT));
            int stride = inU ? CU : CV;
            base[0] = acc[nt][0];
            base[1] = acc[nt][1];
            base[8 * stride]     = acc[nt][2];
            base[8 * stride + 1] = acc[nt][3];
            float s0 = acc[nt][0] + acc[nt][2];
            float s1 = acc[nt][1] + acc[nt][3];
            float t0 = acc[nt][0]*acc[nt][0] + acc[nt][2]*acc[nt][2];
            float t1 = acc[nt][1]*acc[nt][1] + acc[nt][3]*acc[nt][3];
#pragma unroll
            for (int d = 4; d <= 16; d <<= 1) {
                s0 += __shfl_xor_sync(0xFFFFFFFFu, s0, d);
                s1 += __shfl_xor_sync(0xFFFFFFFFu, s1, d);
                t0 += __shfl_xor_sync(0xFFFFFFFFu, t0, d);
                t1 += __shfl_xor_sync(0xFFFFFFFFu, t1, d);
            }
            if (r == 0) {
                pS[wid * NTILE + c0c]     = s0;
                pS[wid * NTILE + c0c + 1] = s1;
                pQ[wid * NTILE + c0c]     = t0;
                pQ[wid * NTILE + c0c + 1] = t1;
            }
        }
    } else {
        int cp = (lane & 3) << 1;
        bool writer = ((lane >> 2) & 3) == 0;
        int gsel = lane >> 4;
        int qout0 = blockIdx.x * 32 + wid * 4;
#pragma unroll
        for (int nt = 0; nt < NT; nt++) {
            float v0 = acc[nt][0], v1 = acc[nt][1];
            float v2 = acc[nt][2], v3 = acc[nt][3];
            if (bias) {
                float b0 = bias[o0 + nt * 8 + cp];
                float b1v = bias[o0 + nt * 8 + cp + 1];
                v0 += b0; v2 += b0; v1 += b1v; v3 += b1v;
            }
#pragma unroll
            for (int d = 4; d <= 8; d <<= 1) {
                v0 = fmaxf(v0, __shfl_xor_sync(0xFFFFFFFFu, v0, d));
                v1 = fmaxf(v1, __shfl_xor_sync(0xFFFFFFFFu, v1, d));
                v2 = fmaxf(v2, __shfl_xor_sync(0xFFFFFFFFu, v2, d));
                v3 = fmaxf(v3, __shfl_xor_sync(0xFFFFFFFFu, v3, d));
            }
            if (writer) {
                int oc0 = o0 + nt * 8 + cp;
                bool inU = (oc0 < OSPLIT);
                int oc = inU ? oc0 : (oc0 - OSPLIT);
                float* outp = inU ? outU : outV;
                int stride = inU ? CU : CV;
                int qa = qout0 + gsel;
                int qb2 = qout0 + 2 + gsel;
                outp[(size_t)qa * stride + oc]      = v0;
                outp[(size_t)qa * stride + oc + 1]  = v1;
                outp[(size_t)qb2 * stride + oc]     = v2;
                outp[(size_t)qb2 * stride + oc + 1] = v3;
            }
            float s0 = v0 + v2, s1 = v1 + v3;
            float t0 = v0 * v0 + v2 * v2, t1 = v1 * v1 + v3 * v3;
            s0 += __shfl_xor_sync(0xFFFFFFFFu, s0, 16);
            s1 += __shfl_xor_sync(0xFFFFFFFFu, s1, 16);
            t0 += __shfl_xor_sync(0xFFFFFFFFu, t0, 16);
            t1 += __shfl_xor_sync(0xFFFFFFFFu, t1, 16);
            if (lane < 4) {
                pS[wid * NTILE + nt * 8 + cp]     = s0;
                pS[wid * NTILE + nt * 8 + cp + 1] = s1;
                pQ[wid * NTILE + nt * 8 + cp]     = t0;
                pQ[wid * NTILE + nt * 8 + cp + 1] = t1;
            }
        }
    }
    __syncthreads();
    if (tid < NTILE) {
        float s = 0.f, q = 0.f;
#pragma unroll
        for (int w = 0; w < 8; w++) { s += pS[w * NTILE + tid]; q += pQ[w * NTILE + tid]; }
        psum[(size_t)blockIdx.x * NSTR + o0 + tid] = s;
        psq [(size_t)blockIdx.x * NSTR + o0 + tid] = q;
    }
}

// ------- final: BN+add+relu, global max (position-major inputs) -------------
__global__ __launch_bounds__(256) void maxfinP_k(
    const float* __restrict__ w2, const float* __restrict__ v2,
    const float* __restrict__ scC, const float* __restrict__ shC,
    const float* __restrict__ scD, const float* __restrict__ shD,
    float* __restrict__ gmax) {
    int b = blockIdx.x, o = threadIdx.x;
    float a = scC[o], c_ = shC[o], d = scD[o], e = shD[o];
    float mx = 0.f;
#pragma unroll 1
    for (int f = 0; f < 5; f++) {
        size_t rowbase = ((size_t)(f * 256 + b) * 32) * 256 + o;
#pragma unroll
        for (int i = 0; i < 32; i++) {
            size_t idx = rowbase + (size_t)i * 256;
            float val = a * w2[idx] + c_ + d * v2[idx] + e;
            mx = fmaxf(mx, fmaxf(val, 0.f));
        }
    }
    gmax[b * 256 + o] = mx;
}

__global__ void fc_k(const float* __restrict__ gmax, const float* __restrict__ fw,
                     const float* __restrict__ fb, float* __restrict__ out) {
    int b = blockIdx.x, tid = threadIdx.x;
    __shared__ float m[256];
    m[tid] = gmax[b * 256 + tid];
    __syncthreads();
    if (tid < 10) {
        float acc = fb[tid];
        for (int o = 0; o < 256; o++) acc += m[o] * fw[tid * 256 + o];
        out[b * 10 + tid] = acc;
    }
}

// ------------------------- launch ------------------------------------------
#define SMK16V 36608
#define SM64V  64000
#define SMENT  86528
#define SM256V 89600

extern "C" void kernel_launch(void* const* d_in, const int* in_sizes, int n_in,
                              void* d_out, int out_size) {
    (void)n_in; (void)out_size;

    const float* x = (const float*)d_in[0];

    float *u1,*v1,*h1,*w1,*u2,*v2,*h2,*w2,*gmax,*ps,*pq,*sc,*sh,*bias2;
    __nv_bfloat16 *whex_hi,*whex_lo,*wb1h_hi,*wb1h_lo,*went_hi,*went_lo;
    __nv_bfloat16 *wc3_hi,*wc3_lo,*wb1c3_hi,*wb1c3_lo,*went2_hi,*went2_lo;
    __nv_bfloat16 *ahi,*alo;
    cudaGetSymbolAddress((void**)&u1, g_u1);
    cudaGetSymbolAddress((void**)&v1, g_v1);
    cudaGetSymbolAddress((void**)&h1, g_h1);
    cudaGetSymbolAddress((void**)&w1, g_w1);
    cudaGetSymbolAddress((void**)&u2, g_u2);
    cudaGetSymbolAddress((void**)&v2, g_v2);
    cudaGetSymbolAddress((void**)&h2, g_h2);
    cudaGetSymbolAddress((void**)&w2, g_w2);
    cudaGetSymbolAddress((void**)&gmax, g_gmax);
    cudaGetSymbolAddress((void**)&ps, g_psum);
    cudaGetSymbolAddress((void**)&pq, g_psq);
    cudaGetSymbolAddress((void**)&sc, g_scale);
    cudaGetSymbolAddress((void**)&sh, g_shift);
    cudaGetSymbolAddress((void**)&bias2, g_bias2);
    cudaGetSymbolAddress((void**)&whex_hi, g_whex_hi);
    cudaGetSymbolAddress((void**)&whex_lo, g_whex_lo);
    cudaGetSymbolAddress((void**)&wb1h_hi, g_wb1h_hi);
    cudaGetSymbolAddress((void**)&wb1h_lo, g_wb1h_lo);
    cudaGetSymbolAddress((void**)&went_hi, g_went_hi);
    cudaGetSymbolAddress((void**)&went_lo, g_went_lo);
    cudaGetSymbolAddress((void**)&wc3_hi, g_wc3_hi);
    cudaGetSymbolAddress((void**)&wc3_lo, g_wc3_lo);
    cudaGetSymbolAddress((void**)&wb1c3_hi, g_wb1c3_hi);
    cudaGetSymbolAddress((void**)&wb1c3_lo, g_wb1c3_lo);
    cudaGetSymbolAddress((void**)&went2_hi, g_went2_hi);
    cudaGetSymbolAddress((void**)&went2_lo, g_went2_lo);
    cudaGetSymbolAddress((void**)&ahi, g_abf_hi);
    cudaGetSymbolAddress((void**)&alo, g_abf_lo);

    // input index tables (runtime disambiguation of metadata order)
    int I_b1c1, I_b1hex, I_b1c3, I_b1ds;
    int I_b1ga, I_b1ba, I_b1gb, I_b1bb, I_b1gc, I_b1bc, I_b1gd, I_b1bd;
    int I_b2c1, I_b2hex, I_b2c3, I_b2ds;
    int I_b2ga, I_b2ba, I_b2gb, I_b2bb, I_b2gc, I_b2bc, I_b2gd, I_b2bd;
    int I_fcw, I_fcb;
    if (in_sizes[5] == 36864) {
        I_b1c1 = 4;  I_b1hex = 5;  I_b1c3 = 6;  I_b1ds = 7;
        I_b1ga = 8;  I_b1ba = 9;  I_b1gb = 10; I_b1bb = 11;
        I_b1gc = 12; I_b1bc = 13; I_b1gd = 14; I_b1bd = 15;
        I_b2c1 = 16; I_b2hex = 17; I_b2c3 = 18; I_b2ds = 19;
        I_b2ga = 20; I_b2ba = 21; I_b2gb = 22; I_b2bb = 23;
        I_b2gc = 24; I_b2bc = 25; I_b2gd = 26; I_b2bd = 27;
        I_fcw = 28;  I_fcb = 29;
    } else {
        I_b1c1 = 4;  I_b1ga = 5;  I_b1ba = 6;  I_b1hex = 7;
        I_b1gb = 8;  I_b1bb = 9;  I_b1c3 = 10; I_b1gc = 11; I_b1bc = 12;
        I_b1ds = 13; I_b1gd = 14; I_b1bd = 15;
        I_b2c1 = 16; I_b2ga = 17; I_b2ba = 18; I_b2hex = 19;
        I_b2gb = 20; I_b2bb = 21; I_b2c3 = 22; I_b2gc = 23; I_b2bc = 24;
        I_b2ds = 25; I_b2gd = 26; I_b2bd = 27;
        I_fcw = 28;  I_fcb = 29;
    }

    // set smem limits for mma instantiations
    cudaFuncSetAttribute(mma_conv_k<16, 128, 1, true, 16, 32, 128, 64, 16, 64, 64, 0>,
                         cudaFuncAttributeMaxDynamicSharedMemorySize, SMK16V);
    cudaFuncSetAttribute(mma_conv_k<512, 64, 7, false, 8, 16, 64, 64, 64, 64, 1, 0>,
                         cudaFuncAttributeMaxDynamicSharedMemorySize, SM64V);
    cudaFuncSetAttribute(mma_conv_k<64, 64, 1, false, 8, 16, 64, 64, 64, 64, 1, 1>,
                         cudaFuncAttributeMaxDynamicSharedMemorySize, SM64V);
    cudaFuncSetAttribute(mma_conv_k<64, 128, 1, true, 8, 16, 512, 256, 64, 256, 256, 2>,
                         cudaFuncAttributeMaxDynamicSharedMemorySize, SMENT);
    cudaFuncSetAttribute(mma_conv_k<2048, 128, 7, false, 4, 8, 256, 256, 256, 256, 1, 0>,
                         cudaFuncAttributeMaxDynamicSharedMemorySize, SM256V);
    cudaFuncSetAttribute(mma_conv_k<256, 128, 1, false, 4, 8, 256, 256, 256, 256, 1, 1>,
                         cudaFuncAttributeMaxDynamicSharedMemorySize, SM256V);

    // weight prep
    hexsplit_k<<<2048, 256>>>((const float*)d_in[I_b2hex], whex_hi, whex_lo, 256, 256);
    hexsplit_k<<<128,  256>>>((const float*)d_in[I_b1hex], wb1h_hi, wb1h_lo, 64, 64);
    split1x1_k<<<64,  256>>>((const float*)d_in[I_b2c1], went_hi, went_lo, 256, 64, 0);
    split1x1_k<<<64,  256>>>((const float*)d_in[I_b2ds], went_hi, went_lo, 256, 64, 256);
    split1x1_k<<<256, 256>>>((const float*)d_in[I_b2c3], wc3_hi, wc3_lo, 256, 256, 0);
    split1x1_k<<<16,  256>>>((const float*)d_in[I_b1c3], wb1c3_hi, wb1c3_lo, 64, 64, 0);

    // stem: hexconv -> relu -> bf16 planes [pos][16] + bn1 stats
    stem_kernel<<<NP0 / 256, 256>>>(x, (const float*)d_in[1], ahi, alo, ps, pq);
    bn_param<<<16, 256>>>(ps, pq, NP0 / 256, 16, 0, 1.f / NP0,
                          (const float*)d_in[2], (const float*)d_in[3], sc + 0, sh + 0);
    foldentry_k<<<1, 128>>>((const float*)d_in[I_b1c1], (const float*)d_in[I_b1ds],
                            sc + 0, sh + 0, went2_hi, went2_lo, bias2);

    // block1 entry (mma, K=16, pooled, bias, N=128 = main||ds, planes AMODE0)
    mma_conv_k<16, 128, 1, true, 16, 32, 128, 64, 16, 64, 64, 0>
        <<<dim3(NP0 / 128, 1), 256, SMK16V>>>(
            ahi, alo, nullptr, nullptr, nullptr, nullptr, nullptr, nullptr,
            went2_hi, went2_lo, bias2, u1, v1, ps, pq);
    bn_param<<<64, 256>>>(ps, pq, NP0 / 128, 128, 0,  1.f / NP1,
                          (const float*)d_in[I_b1ga], (const float*)d_in[I_b1ba], sc + 16,  sh + 16);
    bn_param<<<64, 256>>>(ps, pq, NP0 / 128, 128, 64, 1.f / NP1,
                          (const float*)d_in[I_b1gd], (const float*)d_in[I_b1bd], sc + 208, sh + 208);

    // block1 hexconv (mma, planes from actsplitP(u1))
    actsplitP_k<<<NP1 * 64 / 1024, 256>>>(u1, sc + 16, sh + 16, ahi, alo, 64);
    mma_conv_k<512, 64, 7, false, 8, 16, 64, 64, 64, 64, 1, 0>
        <<<dim3(NP1 / 128, 1), 256, SM64V>>>(
            ahi, alo, nullptr, nullptr, nullptr, nullptr, nullptr, nullptr,
            wb1h_hi, wb1h_lo, nullptr, h1, nullptr, ps, pq);
    bn_param<<<64, 256>>>(ps, pq, NP1 / 128, 64, 0, 1.f / NP1,
                          (const float*)d_in[I_b1gb], (const float*)d_in[I_b1bb], sc + 80, sh + 80);

    // block1 conv3 1x1 (mma, fused affine from h1)
    mma_conv_k<64, 64, 1, false, 8, 16, 64, 64, 64, 64, 1, 1>
        <<<dim3(NP1 / 128, 1), 256, SM64V>>>(
            nullptr, nullptr, h1, nullptr, sc + 80, sh + 80, nullptr, nullptr,
            wb1c3_hi, wb1c3_lo, nullptr, w1, nullptr, ps, pq);
    bn_param<<<64, 256>>>(ps, pq, NP1 / 128, 64, 0, 1.f / NP1,
                          (const float*)d_in[I_b1gc], (const float*)d_in[I_b1bc], sc + 144, sh + 144);

    // block2 entry (mma, dual fused affine from w1+v1, pooled, N=512)
    mma_conv_k<64, 128, 1, true, 8, 16, 512, 256, 64, 256, 256, 2>
        <<<dim3(NP1 / 128, 4), 256, SMENT>>>(
            nullptr, nullptr, w1, v1, sc + 144, sh + 144, sc + 208, sh + 208,
            went_hi, went_lo, nullptr, u2, v2, ps, pq);
    bn_param<<<256, 256>>>(ps, pq, NP1 / 128, 512, 0,   1.f / NP2,
                           (const float*)d_in[I_b2ga], (const float*)d_in[I_b2ba], sc + 272,  sh + 272);
    bn_param<<<256, 256>>>(ps, pq, NP1 / 128, 512, 256, 1.f / NP2,
                           (const float*)d_in[I_b2gd], (const float*)d_in[I_b2bd], sc + 1040, sh + 1040);

    // block2 hexconv (mma, planes from actsplitP(u2))
    actsplitP_k<<<NP2 * 256 / 1024, 256>>>(u2, sc + 272, sh + 272, ahi, alo, 256);
    mma_conv_k<2048, 128, 7, false, 4, 8, 256, 256, 256, 256, 1, 0>
        <<<dim3(NP2 / 128, 2), 256, SM256V>>>(
            ahi, alo, nullptr, nullptr, nullptr, nullptr, nullptr, nullptr,
            whex_hi, whex_lo, nullptr, h2, nullptr, ps, pq);
    bn_param<<<256, 256>>>(ps, pq, NP2 / 128, 256, 0, 1.f / NP2,
                           (const float*)d_in[I_b2gb], (const float*)d_in[I_b2bb], sc + 528, sh + 528);

    // block2 conv3 1x1 (mma, fused affine from h2)
    mma_conv_k<256, 128, 1, false, 4, 8, 256, 256, 256, 256, 1, 1>
        <<<dim3(NP2 / 128, 2), 256, SM256V>>>(
            nullptr, nullptr, h2, nullptr, sc + 528, sh + 528, nullptr, nullptr,
            wc3_hi, wc3_lo, nullptr, w2, nullptr, ps, pq);
    bn_param<<<256, 256>>>(ps, pq, NP2 / 128, 256, 0, 1.f / NP2,
                           (const float*)d_in[I_b2gc], (const float*)d_in[I_b2bc], sc + 784, sh + 784);

    // tail
    maxfinP_k<<<256, 256>>>(w2, v2, sc + 784, sh + 784, sc + 1040, sh + 1040, gmax);
    fc_k<<<256, 256>>>(gmax, (const float*)d_in[I_fcw], (const float*)d_in[I_fcb], (float*)d_out);
}

// round 16
// speedup vs baseline: 1.1719x; 1.0392x over previous
#include <cuda_runtime.h>
#include <cuda_bf16.h>
#include <cstdint>

// Geometry:
//  stage0 in : [5][256][3][16][32]
//  stem out  : 16ch @16x32, NP0 = 5*256*512 = 655360
//  block1    : 64ch @8x16,  NP1 = 5*256*128 = 163840
//  block2    : 256ch@4x8,   NP2 = 5*256*32  = 40960
// ALL activations position-major: fp32 t[pos*C + c]; bf16 planes [pos][C]

#define NP0 655360
#define NP1 163840
#define NP2 40960

// ------------------------- device scratch ----------------------------------
__device__ float g_u1[64 * NP1];
__device__ float g_v1[64 * NP1];
__device__ float g_h1[64 * NP1];
__device__ float g_w1[64 * NP1];
__device__ float g_u2[256 * NP2];
__device__ float g_v2[256 * NP2];
__device__ float g_h2[256 * NP2];
__device__ float g_w2[256 * NP2];
__device__ float g_gmax[256 * 256];

__device__ float g_psum[1310720];
__device__ float g_psq [1310720];

__device__ float g_scale[1296];
__device__ float g_shift[1296];

// split bf16 weights (hex: k = chunk*64 + t*8 + cl, tap7 = 0)
__device__ __nv_bfloat16 g_whex_hi[256 * 2048];
__device__ __nv_bfloat16 g_whex_lo[256 * 2048];
__device__ __nv_bfloat16 g_wb1h_hi[64 * 512];
__device__ __nv_bfloat16 g_wb1h_lo[64 * 512];
__device__ __nv_bfloat16 g_went_hi[512 * 64];
__device__ __nv_bfloat16 g_went_lo[512 * 64];
__device__ __nv_bfloat16 g_wc3_hi [256 * 256];
__device__ __nv_bfloat16 g_wc3_lo [256 * 256];
__device__ __nv_bfloat16 g_wb1c3_hi[64 * 64];
__device__ __nv_bfloat16 g_wb1c3_lo[64 * 64];
// block1 entry: folded (bn1-scaled) weights [128 o][16 c] + bias
__device__ __nv_bfloat16 g_went2_hi[128 * 16];
__device__ __nv_bfloat16 g_went2_lo[128 * 16];
__device__ float g_bias2[128];

// bf16 activation planes [pos][C] (stem / hex / entry inputs; reused sequentially)
__device__ __nv_bfloat16 g_abf_hi[10485760];
__device__ __nv_bfloat16 g_abf_lo[10485760];

// ------------------------- mma helpers -------------------------------------
__device__ __forceinline__ uint32_t smem_u32(const void* p) {
    uint32_t a;
    asm("{ .reg .u64 t; cvta.to.shared.u64 t, %1; cvt.u32.u64 %0, t; }"
        : "=r"(a) : "l"(p));
    return a;
}
__device__ __forceinline__ void ldmA(uint32_t* a, uint32_t addr) {
    asm volatile("ldmatrix.sync.aligned.m8n8.x4.shared.b16 {%0,%1,%2,%3}, [%4];"
        : "=r"(a[0]), "=r"(a[1]), "=r"(a[2]), "=r"(a[3]) : "r"(addr));
}
__device__ __forceinline__ void ldmB(uint32_t* b, uint32_t addr) {
    asm volatile("ldmatrix.sync.aligned.m8n8.x2.shared.b16 {%0,%1}, [%2];"
        : "=r"(b[0]), "=r"(b[1]) : "r"(addr));
}
__device__ __forceinline__ void mma16816(float* d, const uint32_t* a, const uint32_t* b) {
    asm volatile(
        "mma.sync.aligned.m16n8k16.row.col.f32.bf16.bf16.f32 "
        "{%0,%1,%2,%3}, {%4,%5,%6,%7}, {%8,%9}, {%0,%1,%2,%3};"
        : "+f"(d[0]), "+f"(d[1]), "+f"(d[2]), "+f"(d[3])
        : "r"(a[0]), "r"(a[1]), "r"(a[2]), "r"(a[3]), "r"(b[0]), "r"(b[1]));
}

// ------------------------- prep kernels ------------------------------------
__global__ void hexsplit_k(const float* __restrict__ src,
                           __nv_bfloat16* __restrict__ hi, __nv_bfloat16* __restrict__ lo,
                           int O, int C) {
    int i = blockIdx.x * 256 + threadIdx.x;
    if (i < O * C * 8) {
        int t = i & 7;
        int c = (i >> 3) % C;
        int o = i / (8 * C);
        float w = (t < 7) ? src[(o * C + c) * 9 + t + 1] : 0.f;
        __nv_bfloat16 h = __float2bfloat16(w);
        int k = (c >> 3) * 64 + t * 8 + (c & 7);
        hi[(size_t)o * (C * 8) + k] = h;
        lo[(size_t)o * (C * 8) + k] = __float2bfloat16(w - __bfloat162float(h));
    }
}

__global__ void split1x1_k(const float* __restrict__ src,
                           __nv_bfloat16* __restrict__ hi, __nv_bfloat16* __restrict__ lo,
                           int O, int C, int rowoff) {
    int i = blockIdx.x * 256 + threadIdx.x;
    if (i < O * C) {
        float w = src[i];
        __nv_bfloat16 h = __float2bfloat16(w);
        int o = i / C, c = i % C;
        hi[(rowoff + o) * C + c] = h;
        lo[(rowoff + o) * C + c] = __float2bfloat16(w - __bfloat162float(h));
    }
}

// fold bn1 affine into block1-entry weights: w' = w*s_c, bias = sum w*t_c
__global__ void foldentry_k(const float* __restrict__ c1w, const float* __restrict__ dsw,
                            const float* __restrict__ sc0, const float* __restrict__ sh0,
                            __nv_bfloat16* __restrict__ hi, __nv_bfloat16* __restrict__ lo,
                            float* __restrict__ bias) {
    int o = threadIdx.x;  // 128
    const float* src = (o < 64) ? (c1w + o * 16) : (dsw + (o - 64) * 16);
    float b = 0.f;
    for (int c = 0; c < 16; c++) {
        float w = src[c] * sc0[c];
        b += src[c] * sh0[c];
        __nv_bfloat16 h = __float2bfloat16(w);
        hi[o * 16 + c] = h;
        lo[o * 16 + c] = __float2bfloat16(w - __bfloat162float(h));
    }
    bias[o] = b;
}

// relu(sc*x+sh), position-major fp32 [pos][C] -> bf16 hi/lo [pos][C]
__global__ __launch_bounds__(256) void actsplitP_k(
    const float* __restrict__ x, const float* __restrict__ sc,
    const float* __restrict__ sh,
    __nv_bfloat16* __restrict__ hi, __nv_bfloat16* __restrict__ lo, int C) {
    size_t i = (size_t)blockIdx.x * 256 + threadIdx.x;   // quad index
    float4 v4 = *(const float4*)(x + i * 4);
    int c0 = (int)((i * 4) % C);
    float v[4] = {v4.x, v4.y, v4.z, v4.w};
    __align__(8) __nv_bfloat16 h4[4], l4[4];
#pragma unroll
    for (int j = 0; j < 4; j++) {
        float vv = fmaxf(sc[c0 + j] * v[j] + sh[c0 + j], 0.f);
        __nv_bfloat16 hb = __float2bfloat16(vv);
        h4[j] = hb;
        l4[j] = __float2bfloat16(vv - __bfloat162float(hb));
    }
    *(uint2*)(hi + i * 4) = *(uint2*)h4;
    *(uint2*)(lo + i * 4) = *(uint2*)l4;
}

// relu(s1*a+t1 + s2*b+t2), dual position-major inputs -> bf16 hi/lo
__global__ __launch_bounds__(256) void actsplit2P_k(
    const float* __restrict__ xa, const float* __restrict__ xb,
    const float* __restrict__ s1, const float* __restrict__ t1,
    const float* __restrict__ s2, const float* __restrict__ t2,
    __nv_bfloat16* __restrict__ hi, __nv_bfloat16* __restrict__ lo, int C) {
    size_t i = (size_t)blockIdx.x * 256 + threadIdx.x;
    float4 a4 = *(const float4*)(xa + i * 4);
    float4 b4 = *(const float4*)(xb + i * 4);
    int c0 = (int)((i * 4) % C);
    float av[4] = {a4.x, a4.y, a4.z, a4.w};
    float bv[4] = {b4.x, b4.y, b4.z, b4.w};
    __align__(8) __nv_bfloat16 h4[4], l4[4];
#pragma unroll
    for (int j = 0; j < 4; j++) {
        float vv = fmaxf(s1[c0 + j] * av[j] + t1[c0 + j]
                       + s2[c0 + j] * bv[j] + t2[c0 + j], 0.f);
        __nv_bfloat16 hb = __float2bfloat16(vv);
        h4[j] = hb;
        l4[j] = __float2bfloat16(vv - __bfloat162float(hb));
    }
    *(uint2*)(hi + i * 4) = *(uint2*)h4;
    *(uint2*)(lo + i * 4) = *(uint2*)l4;
}

// ------------------------- stem: hexconv -> relu -> bf16 planes -------------
__global__ __launch_bounds__(256) void stem_kernel(
    const float* __restrict__ x, const float* __restrict__ wc,
    __nv_bfloat16* __restrict__ ahi, __nv_bfloat16* __restrict__ alo,
    float* __restrict__ psum, float* __restrict__ psq) {
    __shared__ float wsh[432];
    __shared__ float wpS[16][8], wpQ[16][8];
    int tid = threadIdx.x;
    for (int e = tid; e < 432; e += 256) wsh[e] = wc[e];
    __syncthreads();

    int pos = blockIdx.x * 256 + tid;
    int w = pos & 31, h = (pos >> 5) & 15, b = (pos >> 9) & 255, f = pos >> 17;

    float acc[16];
#pragma unroll
    for (int o = 0; o < 16; o++) acc[o] = 0.f;

#pragma unroll
    for (int t = 0; t < 7; t++) {
        int kf = t + 1;
        int dy = kf / 3 - 1, dx = kf % 3 - 1;
        int hh = h + dy;
        float xv0 = 0.f, xv1 = 0.f, xv2 = 0.f;
        if (hh >= 0 && hh < 16) {
            int ww = w + dx, ff = f;
            if (ww < 0)       { ff = (f + 4) % 5; ww = 31; }
            else if (ww > 31) { ff = (f + 1) % 5; ww = 0;  }
            int base = (ff * 256 + b) * 1536 + hh * 32 + ww;
            xv0 = x[base];
            xv1 = x[base + 512];
            xv2 = x[base + 1024];
        }
#pragma unroll
        for (int o = 0; o < 16; o++) {
            acc[o] += wsh[(o * 3 + 0) * 9 + kf] * xv0
                    + wsh[(o * 3 + 1) * 9 + kf] * xv1
                    + wsh[(o * 3 + 2) * 9 + kf] * xv2;
        }
    }

    __align__(16) __nv_bfloat16 h16[16];
    __align__(16) __nv_bfloat16 l16[16];
    int lane = tid & 31, warp = tid >> 5;
#pragma unroll
    for (int o = 0; o < 16; o++) {
        float val = fmaxf(acc[o], 0.f);
        __nv_bfloat16 hb = __float2bfloat16(val);
        h16[o] = hb;
        l16[o] = __float2bfloat16(val - __bfloat162float(hb));
        float s = val, q2 = val * val;
#pragma unroll
        for (int d = 16; d; d >>= 1) {
            s  += __shfl_xor_sync(0xFFFFFFFFu, s,  d);
            q2 += __shfl_xor_sync(0xFFFFFFFFu, q2, d);
        }
        if (lane == 0) { wpS[o][warp] = s; wpQ[o][warp] = q2; }
    }
    *(uint4*)(ahi + (size_t)pos * 16)     = *(uint4*)h16;
    *(uint4*)(ahi + (size_t)pos * 16 + 8) = *(uint4*)(h16 + 8);
    *(uint4*)(alo + (size_t)pos * 16)     = *(uint4*)l16;
    *(uint4*)(alo + (size_t)pos * 16 + 8) = *(uint4*)(l16 + 8);

    __syncthreads();
    if (tid < 16) {
        float s = 0.f, q = 0.f;
#pragma unroll
        for (int wpi = 0; wpi < 8; wpi++) { s += wpS[tid][wpi]; q += wpQ[tid][wpi]; }
        psum[blockIdx.x * 16 + tid] = s;
        psq [blockIdx.x * 16 + tid] = q;
    }
}

// ------------------------- BN param fold ------------------------------------
__global__ void bn_param(const float* __restrict__ ps, const float* __restrict__ pq,
                         int nparts, int cstride, int coff, float invN,
                         const float* __restrict__ g, const float* __restrict__ b,
                         float* __restrict__ sc, float* __restrict__ sh) {
    int c = blockIdx.x, tid = threadIdx.x;
    float s = 0.f, q = 0.f;
    for (int p = tid; p < nparts; p += 256) {
        s += ps[(size_t)p * cstride + coff + c];
        q += pq[(size_t)p * cstride + coff + c];
    }
    __shared__ float rs[256], rq[256];
    rs[tid] = s; rq[tid] = q;
    __syncthreads();
    for (int d = 128; d; d >>= 1) {
        if (tid < d) { rs[tid] += rs[tid + d]; rq[tid] += rq[tid + d]; }
        __syncthreads();
    }
    if (tid == 0) {
        float mean = rs[0] * invN;
        float var  = rq[0] * invN - mean * mean;
        float k = g[c] * rsqrtf(var + 1e-5f);
        sc[c] = k;
        sh[c] = b[c] - mean * k;
    }
}

// ---------------- generic mma.sync split-bf16 conv/GEMM ---------------------
// D[m=128, o=NTILE] = A[m, k] * W[o, k].
// AMODE 0: A from bf16 planes ahi/alo [pos][CDIM].
// AMODE 1: A = relu(scA*xf1+shA) fused at staging (fp32 [pos][CDIM]).
// Outputs POSITION-MAJOR fp32: oc<OSPLIT -> outU[q*CU+oc] else outV[q*CV+oc-OSPLIT].
template <int KTOT, int NTILE, int TAPS, bool POOL, int HIN, int WIN,
          int NSTR, int OSPLIT, int CDIM, int CU, int CV, int AMODE>
__global__ __launch_bounds__(256) void mma_conv_k(
    const __nv_bfloat16* __restrict__ ahi, const __nv_bfloat16* __restrict__ alo,
    const float* __restrict__ xf1,
    const float* __restrict__ scA, const float* __restrict__ shA,
    const __nv_bfloat16* __restrict__ whi, const __nv_bfloat16* __restrict__ wlo,
    const float* __restrict__ bias,
    float* __restrict__ outU, float* __restrict__ outV,
    float* __restrict__ psum, float* __restrict__ psq) {
    constexpr int NT = NTILE / 8;
    constexpr int KCH = (KTOT < 64) ? KTOT : 64;
    constexpr int NCHUNK = KTOT / KCH;
    constexpr int LDAv = KCH + 8;
    constexpr int GPR = KCH / 8;
    constexpr int KS = KCH / 16;
    constexpr int AITERS = (128 * GPR) / 256;
    constexpr int BITERS = (NTILE * GPR + 255) / 256;
    constexpr int OF_SC = 3584;
    constexpr int OF_AH = OF_SC + 2 * CDIM * 4;
    constexpr int OF_AL = OF_AH + 128 * LDAv * 2;
    constexpr int OF_BH = OF_AL + 128 * LDAv * 2;
    constexpr int OF_BL = OF_BH + NTILE * LDAv * 2;
    constexpr int OF_PS = OF_BL + NTILE * LDAv * 2;
    constexpr int OF_PQ = OF_PS + NTILE * 32;

    extern __shared__ __align__(16) char smem[];
    uint32_t sb = smem_u32(smem);
    int tid = threadIdx.x;
    int wid = tid >> 5, lane = tid & 31;
    int q0 = blockIdx.x * 128;
    int o0 = blockIdx.y * NTILE;

    int* nbr = (int*)(smem);
    for (int e = tid; e < TAPS * 128; e += 256) {
        int t = e >> 7, ql = e & 127;
        int m = q0 + ql;
        int pos;
        if (POOL) {
            constexpr int WO = WIN / 2, HO = HIN / 2;
            int qq = m >> 2, sub = m & 3;
            int w = qq % WO;
            int h = (qq / WO) % HO;
            int fb = qq / (WO * HO);
            pos = (fb * HIN + 2 * h + (sub >> 1)) * WIN + 2 * w + (sub & 1);
        } else if (TAPS == 1) {
            pos = m;
        } else {
            int w = m % WIN;
            int h = (m / WIN) % HIN;
            int b = (m / (WIN * HIN)) & 255;
            int f = m / (WIN * HIN * 256);
            int kf = t + 1;
            int dy = kf / 3 - 1, dx = kf % 3 - 1;
            int hh = h + dy, ww = w + dx, ff = f;
            if (hh < 0 || hh >= HIN) pos = -1;
            else {
                if (ww < 0)        { ff = (f + 4) % 5; ww = WIN - 1; }
                else if (ww >= WIN){ ff = (f + 1) % 5; ww = 0;       }
                pos = ((ff * 256 + b) * HIN + hh) * WIN + ww;
            }
        }
        nbr[t * 128 + ql] = pos;
    }
    float* scS = (float*)(smem + OF_SC);
    float* shS = scS + CDIM;
    if (AMODE == 1) {
        for (int c = tid; c < CDIM; c += 256) {
            scS[c] = scA[c];
            shS[c] = shA[c];
        }
    }
    __syncthreads();

    float acc[NT][4];
#pragma unroll
    for (int nt = 0; nt < NT; nt++)
#pragma unroll
        for (int j = 0; j < 4; j++) acc[nt][j] = 0.f;

    int m0 = wid * 16;
    int grp = lane >> 3;
    int rowA = m0 + (lane & 7) + (grp & 1) * 8;
    int colA8 = (grp >> 1) * 8;
    uint32_t aBaseH = sb + OF_AH + (uint32_t)(rowA * LDAv + colA8) * 2;
    uint32_t aBaseL = sb + OF_AL + (uint32_t)(rowA * LDAv + colA8) * 2;
    int rowB = (lane & 7);
    int colB8 = ((lane >> 3) & 1) * 8;
    uint32_t bBaseH = sb + OF_BH + (uint32_t)(rowB * LDAv + colB8) * 2;
    uint32_t bBaseL = sb + OF_BL + (uint32_t)(rowB * LDAv + colB8) * 2;

    __nv_bfloat16* AH = (__nv_bfloat16*)(smem + OF_AH);
    __nv_bfloat16* AL = (__nv_bfloat16*)(smem + OF_AL);
    __nv_bfloat16* BH = (__nv_bfloat16*)(smem + OF_BH);
    __nv_bfloat16* BL = (__nv_bfloat16*)(smem + OF_BL);

#pragma unroll 1
    for (int ci = 0; ci < NCHUNK; ci++) {
        // stage A: [128 m][KCH k]
#pragma unroll
        for (int it = 0; it < AITERS; it++) {
            int e = it * 256 + tid;
            int q = e / GPR, g = e % GPR;
            int pos = -1, c0;
            if (TAPS == 7) { c0 = ci * 8; if (g < 7) pos = nbr[g * 128 + q]; }
            else           { c0 = ci * KCH + g * 8; pos = nbr[q]; }
            if (AMODE == 0) {
                uint4 vh = {0u, 0u, 0u, 0u}, vl = {0u, 0u, 0u, 0u};
                if (pos >= 0) {
                    size_t base = (size_t)pos * CDIM + c0;
                    vh = *(const uint4*)(ahi + base);
                    vl = *(const uint4*)(alo + base);
                }
                *(uint4*)(AH + q * LDAv + g * 8) = vh;
                *(uint4*)(AL + q * LDAv + g * 8) = vl;
            } else {
                float v[8] = {0.f, 0.f, 0.f, 0.f, 0.f, 0.f, 0.f, 0.f};
                if (pos >= 0) {
                    const float* p1 = xf1 + (size_t)pos * CDIM + c0;
                    float4 f0 = *(const float4*)p1;
                    float4 f1 = *(const float4*)(p1 + 4);
                    float r1[8] = {f0.x, f0.y, f0.z, f0.w, f1.x, f1.y, f1.z, f1.w};
#pragma unroll
                    for (int j = 0; j < 8; j++)
                        v[j] = fmaxf(scS[c0 + j] * r1[j] + shS[c0 + j], 0.f);
                }
                __align__(16) __nv_bfloat16 h8[8], l8[8];
#pragma unroll
                for (int j = 0; j < 8; j++) {
                    __nv_bfloat16 hb = __float2bfloat16(v[j]);
                    h8[j] = hb;
                    l8[j] = __float2bfloat16(v[j] - __bfloat162float(hb));
                }
                *(uint4*)(AH + q * LDAv + g * 8) = *(uint4*)h8;
                *(uint4*)(AL + q * LDAv + g * 8) = *(uint4*)l8;
            }
        }
        // stage B: [NTILE o][KCH k]
#pragma unroll
        for (int it = 0; it < BITERS; it++) {
            int e = it * 256 + tid;
            if (e < NTILE * GPR) {
                int o = e / GPR, j = e % GPR;
                size_t src = (size_t)(o0 + o) * KTOT + ci * KCH + j * 8;
                *(uint4*)(BH + o * LDAv + j * 8) = *(const uint4*)(whi + src);
                *(uint4*)(BL + o * LDAv + j * 8) = *(const uint4*)(wlo + src);
            }
        }
        __syncthreads();

#pragma unroll
        for (int ks = 0; ks < KS; ks++) {
            uint32_t aH[4], aL[4];
            ldmA(aH, aBaseH + ks * 32);
            ldmA(aL, aBaseL + ks * 32);
#pragma unroll
            for (int nt = 0; nt < NT; nt++) {
                uint32_t bH[2], bL[2];
                uint32_t boff = (uint32_t)(nt * 8 * LDAv) * 2 + ks * 32;
                ldmB(bH, bBaseH + boff);
                ldmB(bL, bBaseL + boff);
                mma16816(acc[nt], aH, bH);
                mma16816(acc[nt], aL, bH);
                mma16816(acc[nt], aH, bL);
            }
        }
        __syncthreads();
    }

    float* pS = (float*)(smem + OF_PS);
    float* pQ = (float*)(smem + OF_PQ);

    if (!POOL) {
        int r = lane >> 2;
        int cp = (lane & 3) << 1;
#pragma unroll
        for (int nt = 0; nt < NT; nt++) {
            int c0c = nt * 8 + cp;
            int qrow = q0 + m0 + r;
            int oc0 = o0 + c0c;
            bool inU = (oc0 < OSPLIT);
            float* base = inU ? (outU + (size_t)qrow * CU + oc0)
                              : (outV + (size_t)qrow * CV + (oc0 - OSPLIT));
            int stride = inU ? CU : CV;
            base[0] = acc[nt][0];
            base[1] = acc[nt][1];
            base[8 * stride]     = acc[nt][2];
            base[8 * stride + 1] = acc[nt][3];
            float s0 = acc[nt][0] + acc[nt][2];
            float s1 = acc[nt][1] + acc[nt][3];
            float t0 = acc[nt][0]*acc[nt][0] + acc[nt][2]*acc[nt][2];
            float t1 = acc[nt][1]*acc[nt][1] + acc[nt][3]*acc[nt][3];
#pragma unroll
            for (int d = 4; d <= 16; d <<= 1) {
                s0 += __shfl_xor_sync(0xFFFFFFFFu, s0, d);
                s1 += __shfl_xor_sync(0xFFFFFFFFu, s1, d);
                t0 += __shfl_xor_sync(0xFFFFFFFFu, t0, d);
                t1 += __shfl_xor_sync(0xFFFFFFFFu, t1, d);
            }
            if (r == 0) {
                pS[wid * NTILE + c0c]     = s0;
                pS[wid * NTILE + c0c + 1] = s1;
                pQ[wid * NTILE + c0c]     = t0;
                pQ[wid * NTILE + c0c + 1] = t1;
            }
        }
    } else {
        int cp = (lane & 3) << 1;
        bool writer = ((lane >> 2) & 3) == 0;
        int gsel = lane >> 4;
        int qout0 = blockIdx.x * 32 + wid * 4;
#pragma unroll
        for (int nt = 0; nt < NT; nt++) {
            float v0 = acc[nt][0], v1 = acc[nt][1];
            float v2 = acc[nt][2], v3 = acc[nt][3];
            if (bias) {
                float b0 = bias[o0 + nt * 8 + cp];
                float b1v = bias[o0 + nt * 8 + cp + 1];
                v0 += b0; v2 += b0; v1 += b1v; v3 += b1v;
            }
#pragma unroll
            for (int d = 4; d <= 8; d <<= 1) {
                v0 = fmaxf(v0, __shfl_xor_sync(0xFFFFFFFFu, v0, d));
                v1 = fmaxf(v1, __shfl_xor_sync(0xFFFFFFFFu, v1, d));
                v2 = fmaxf(v2, __shfl_xor_sync(0xFFFFFFFFu, v2, d));
                v3 = fmaxf(v3, __shfl_xor_sync(0xFFFFFFFFu, v3, d));
            }
            if (writer) {
                int oc0 = o0 + nt * 8 + cp;
                bool inU = (oc0 < OSPLIT);
                int oc = inU ? oc0 : (oc0 - OSPLIT);
                float* outp = inU ? outU : outV;
                int stride = inU ? CU : CV;
                int qa = qout0 + gsel;
                int qb2 = qout0 + 2 + gsel;
                outp[(size_t)qa * stride + oc]      = v0;
                outp[(size_t)qa * stride + oc + 1]  = v1;
                outp[(size_t)qb2 * stride + oc]     = v2;
                outp[(size_t)qb2 * stride + oc + 1] = v3;
            }
            float s0 = v0 + v2, s1 = v1 + v3;
            float t0 = v0 * v0 + v2 * v2, t1 = v1 * v1 + v3 * v3;
            s0 += __shfl_xor_sync(0xFFFFFFFFu, s0, 16);
            s1 += __shfl_xor_sync(0xFFFFFFFFu, s1, 16);
            t0 += __shfl_xor_sync(0xFFFFFFFFu, t0, 16);
            t1 += __shfl_xor_sync(0xFFFFFFFFu, t1, 16);
            if (lane < 4) {
                pS[wid * NTILE + nt * 8 + cp]     = s0;
                pS[wid * NTILE + nt * 8 + cp + 1] = s1;
                pQ[wid * NTILE + nt * 8 + cp]     = t0;
                pQ[wid * NTILE + nt * 8 + cp + 1] = t1;
            }
        }
    }
    __syncthreads();
    if (tid < NTILE) {
        float s = 0.f, q = 0.f;
#pragma unroll
        for (int w = 0; w < 8; w++) { s += pS[w * NTILE + tid]; q += pQ[w * NTILE + tid]; }
        psum[(size_t)blockIdx.x * NSTR + o0 + tid] = s;
        psq [(size_t)blockIdx.x * NSTR + o0 + tid] = q;
    }
}

// ------- final: BN+add+relu, global max (position-major inputs) -------------
__global__ __launch_bounds__(256) void maxfinP_k(
    const float* __restrict__ w2, const float* __restrict__ v2,
    const float* __restrict__ scC, const float* __restrict__ shC,
    const float* __restrict__ scD, const float* __restrict__ shD,
    float* __restrict__ gmax) {
    int b = blockIdx.x, o = threadIdx.x;
    float a = scC[o], c_ = shC[o], d = scD[o], e = shD[o];
    float mx = 0.f;
#pragma unroll 1
    for (int f = 0; f < 5; f++) {
        size_t rowbase = ((size_t)(f * 256 + b) * 32) * 256 + o;
#pragma unroll
        for (int i = 0; i < 32; i++) {
            size_t idx = rowbase + (size_t)i * 256;
            float val = a * w2[idx] + c_ + d * v2[idx] + e;
            mx = fmaxf(mx, fmaxf(val, 0.f));
        }
    }
    gmax[b * 256 + o] = mx;
}

__global__ void fc_k(const float* __restrict__ gmax, const float* __restrict__ fw,
                     const float* __restrict__ fb, float* __restrict__ out) {
    int b = blockIdx.x, tid = threadIdx.x;
    __shared__ float m[256];
    m[tid] = gmax[b * 256 + tid];
    __syncthreads();
    if (tid < 10) {
        float acc = fb[tid];
        for (int o = 0; o < 256; o++) acc += m[o] * fw[tid * 256 + o];
        out[b * 10 + tid] = acc;
    }
}

// ------------------------- launch ------------------------------------------
#define SMK16V 36480
#define SM64V  63488
#define SMENT  86016
#define SM256V 88576

extern "C" void kernel_launch(void* const* d_in, const int* in_sizes, int n_in,
                              void* d_out, int out_size) {
    (void)n_in; (void)out_size;

    const float* x = (const float*)d_in[0];

    float *u1,*v1,*h1,*w1,*u2,*v2,*h2,*w2,*gmax,*ps,*pq,*sc,*sh,*bias2;
    __nv_bfloat16 *whex_hi,*whex_lo,*wb1h_hi,*wb1h_lo,*went_hi,*went_lo;
    __nv_bfloat16 *wc3_hi,*wc3_lo,*wb1c3_hi,*wb1c3_lo,*went2_hi,*went2_lo;
    __nv_bfloat16 *ahi,*alo;
    cudaGetSymbolAddress((void**)&u1, g_u1);
    cudaGetSymbolAddress((void**)&v1, g_v1);
    cudaGetSymbolAddress((void**)&h1, g_h1);
    cudaGetSymbolAddress((void**)&w1, g_w1);
    cudaGetSymbolAddress((void**)&u2, g_u2);
    cudaGetSymbolAddress((void**)&v2, g_v2);
    cudaGetSymbolAddress((void**)&h2, g_h2);
    cudaGetSymbolAddress((void**)&w2, g_w2);
    cudaGetSymbolAddress((void**)&gmax, g_gmax);
    cudaGetSymbolAddress((void**)&ps, g_psum);
    cudaGetSymbolAddress((void**)&pq, g_psq);
    cudaGetSymbolAddress((void**)&sc, g_scale);
    cudaGetSymbolAddress((void**)&sh, g_shift);
    cudaGetSymbolAddress((void**)&bias2, g_bias2);
    cudaGetSymbolAddress((void**)&whex_hi, g_whex_hi);
    cudaGetSymbolAddress((void**)&whex_lo, g_whex_lo);
    cudaGetSymbolAddress((void**)&wb1h_hi, g_wb1h_hi);
    cudaGetSymbolAddress((void**)&wb1h_lo, g_wb1h_lo);
    cudaGetSymbolAddress((void**)&went_hi, g_went_hi);
    cudaGetSymbolAddress((void**)&went_lo, g_went_lo);
    cudaGetSymbolAddress((void**)&wc3_hi, g_wc3_hi);
    cudaGetSymbolAddress((void**)&wc3_lo, g_wc3_lo);
    cudaGetSymbolAddress((void**)&wb1c3_hi, g_wb1c3_hi);
    cudaGetSymbolAddress((void**)&wb1c3_lo, g_wb1c3_lo);
    cudaGetSymbolAddress((void**)&went2_hi, g_went2_hi);
    cudaGetSymbolAddress((void**)&went2_lo, g_went2_lo);
    cudaGetSymbolAddress((void**)&ahi, g_abf_hi);
    cudaGetSymbolAddress((void**)&alo, g_abf_lo);

    // input index tables (runtime disambiguation of metadata order)
    int I_b1c1, I_b1hex, I_b1c3, I_b1ds;
    int I_b1ga, I_b1ba, I_b1gb, I_b1bb, I_b1gc, I_b1bc, I_b1gd, I_b1bd;
    int I_b2c1, I_b2hex, I_b2c3, I_b2ds;
    int I_b2ga, I_b2ba, I_b2gb, I_b2bb, I_b2gc, I_b2bc, I_b2gd, I_b2bd;
    int I_fcw, I_fcb;
    if (in_sizes[5] == 36864) {
        I_b1c1 = 4;  I_b1hex = 5;  I_b1c3 = 6;  I_b1ds = 7;
        I_b1ga = 8;  I_b1ba = 9;  I_b1gb = 10; I_b1bb = 11;
        I_b1gc = 12; I_b1bc = 13; I_b1gd = 14; I_b1bd = 15;
        I_b2c1 = 16; I_b2hex = 17; I_b2c3 = 18; I_b2ds = 19;
        I_b2ga = 20; I_b2ba = 21; I_b2gb = 22; I_b2bb = 23;
        I_b2gc = 24; I_b2bc = 25; I_b2gd = 26; I_b2bd = 27;
        I_fcw = 28;  I_fcb = 29;
    } else {
        I_b1c1 = 4;  I_b1ga = 5;  I_b1ba = 6;  I_b1hex = 7;
        I_b1gb = 8;  I_b1bb = 9;  I_b1c3 = 10; I_b1gc = 11; I_b1bc = 12;
        I_b1ds = 13; I_b1gd = 14; I_b1bd = 15;
        I_b2c1 = 16; I_b2ga = 17; I_b2ba = 18; I_b2hex = 19;
        I_b2gb = 20; I_b2bb = 21; I_b2c3 = 22; I_b2gc = 23; I_b2bc = 24;
        I_b2ds = 25; I_b2gd = 26; I_b2bd = 27;
        I_fcw = 28;  I_fcb = 29;
    }

    // set smem limits for mma instantiations
    cudaFuncSetAttribute(mma_conv_k<16, 128, 1, true, 16, 32, 128, 64, 16, 64, 64, 0>,
                         cudaFuncAttributeMaxDynamicSharedMemorySize, SMK16V);
    cudaFuncSetAttribute(mma_conv_k<512, 64, 7, false, 8, 16, 64, 64, 64, 64, 1, 0>,
                         cudaFuncAttributeMaxDynamicSharedMemorySize, SM64V);
    cudaFuncSetAttribute(mma_conv_k<64, 64, 1, false, 8, 16, 64, 64, 64, 64, 1, 1>,
                         cudaFuncAttributeMaxDynamicSharedMemorySize, SM64V);
    cudaFuncSetAttribute(mma_conv_k<64, 128, 1, true, 8, 16, 512, 256, 64, 256, 256, 0>,
                         cudaFuncAttributeMaxDynamicSharedMemorySize, SMENT);
    cudaFuncSetAttribute(mma_conv_k<2048, 128, 7, false, 4, 8, 256, 256, 256, 256, 1, 0>,
                         cudaFuncAttributeMaxDynamicSharedMemorySize, SM256V);
    cudaFuncSetAttribute(mma_conv_k<256, 128, 1, false, 4, 8, 256, 256, 256, 256, 1, 1>,
                         cudaFuncAttributeMaxDynamicSharedMemorySize, SM256V);

    // weight prep
    hexsplit_k<<<2048, 256>>>((const float*)d_in[I_b2hex], whex_hi, whex_lo, 256, 256);
    hexsplit_k<<<128,  256>>>((const float*)d_in[I_b1hex], wb1h_hi, wb1h_lo, 64, 64);
    split1x1_k<<<64,  256>>>((const float*)d_in[I_b2c1], went_hi, went_lo, 256, 64, 0);
    split1x1_k<<<64,  256>>>((const float*)d_in[I_b2ds], went_hi, went_lo, 256, 64, 256);
    split1x1_k<<<256, 256>>>((const float*)d_in[I_b2c3], wc3_hi, wc3_lo, 256, 256, 0);
    split1x1_k<<<16,  256>>>((const float*)d_in[I_b1c3], wb1c3_hi, wb1c3_lo, 64, 64, 0);

    // stem: hexconv -> relu -> bf16 planes [pos][16] + bn1 stats
    stem_kernel<<<NP0 / 256, 256>>>(x, (const float*)d_in[1], ahi, alo, ps, pq);
    bn_param<<<16, 256>>>(ps, pq, NP0 / 256, 16, 0, 1.f / NP0,
                          (const float*)d_in[2], (const float*)d_in[3], sc + 0, sh + 0);
    foldentry_k<<<1, 128>>>((const float*)d_in[I_b1c1], (const float*)d_in[I_b1ds],
                            sc + 0, sh + 0, went2_hi, went2_lo, bias2);

    // block1 entry (mma, K=16, pooled, bias, N=128 = main||ds, planes AMODE0)
    mma_conv_k<16, 128, 1, true, 16, 32, 128, 64, 16, 64, 64, 0>
        <<<dim3(NP0 / 128, 1), 256, SMK16V>>>(
            ahi, alo, nullptr, nullptr, nullptr,
            went2_hi, went2_lo, bias2, u1, v1, ps, pq);
    bn_param<<<64, 256>>>(ps, pq, NP0 / 128, 128, 0,  1.f / NP1,
                          (const float*)d_in[I_b1ga], (const float*)d_in[I_b1ba], sc + 16,  sh + 16);
    bn_param<<<64, 256>>>(ps, pq, NP0 / 128, 128, 64, 1.f / NP1,
                          (const float*)d_in[I_b1gd], (const float*)d_in[I_b1bd], sc + 208, sh + 208);

    // block1 hexconv (mma, planes from actsplitP(u1))
    actsplitP_k<<<NP1 * 64 / 1024, 256>>>(u1, sc + 16, sh + 16, ahi, alo, 64);
    mma_conv_k<512, 64, 7, false, 8, 16, 64, 64, 64, 64, 1, 0>
        <<<dim3(NP1 / 128, 1), 256, SM64V>>>(
            ahi, alo, nullptr, nullptr, nullptr,
            wb1h_hi, wb1h_lo, nullptr, h1, nullptr, ps, pq);
    bn_param<<<64, 256>>>(ps, pq, NP1 / 128, 64, 0, 1.f / NP1,
                          (const float*)d_in[I_b1gb], (const float*)d_in[I_b1bb], sc + 80, sh + 80);

    // block1 conv3 1x1 (mma, fused affine from h1; o-tiles = 1)
    mma_conv_k<64, 64, 1, false, 8, 16, 64, 64, 64, 64, 1, 1>
        <<<dim3(NP1 / 128, 1), 256, SM64V>>>(
            nullptr, nullptr, h1, sc + 80, sh + 80,
            wb1c3_hi, wb1c3_lo, nullptr, w1, nullptr, ps, pq);
    bn_param<<<64, 256>>>(ps, pq, NP1 / 128, 64, 0, 1.f / NP1,
                          (const float*)d_in[I_b1gc], (const float*)d_in[I_b1bc], sc + 144, sh + 144);

    // block2 entry (mma, planes from actsplit2P(w1,v1), pooled, N=512)
    actsplit2P_k<<<NP1 * 64 / 1024, 256>>>(w1, v1, sc + 144, sh + 144,
                                           sc + 208, sh + 208, ahi, alo, 64);
    mma_conv_k<64, 128, 1, true, 8, 16, 512, 256, 64, 256, 256, 0>
        <<<dim3(NP1 / 128, 4), 256, SMENT>>>(
            ahi, alo, nullptr, nullptr, nullptr,
            went_hi, went_lo, nullptr, u2, v2, ps, pq);
    bn_param<<<256, 256>>>(ps, pq, NP1 / 128, 512, 0,   1.f / NP2,
                           (const float*)d_in[I_b2ga], (const float*)d_in[I_b2ba], sc + 272,  sh + 272);
    bn_param<<<256, 256>>>(ps, pq, NP1 / 128, 512, 256, 1.f / NP2,
                           (const float*)d_in[I_b2gd], (const float*)d_in[I_b2bd], sc + 1040, sh + 1040);

    // block2 hexconv (mma, planes from actsplitP(u2))
    actsplitP_k<<<NP2 * 256 / 1024, 256>>>(u2, sc + 272, sh + 272, ahi, alo, 256);
    mma_conv_k<2048, 128, 7, false, 4, 8, 256, 256, 256, 256, 1, 0>
        <<<dim3(NP2 / 128, 2), 256, SM256V>>>(
            ahi, alo, nullptr, nullptr, nullptr,
            whex_hi, whex_lo, nullptr, h2, nullptr, ps, pq);
    bn_param<<<256, 256>>>(ps, pq, NP2 / 128, 256, 0, 1.f / NP2,
                           (const float*)d_in[I_b2gb], (const float*)d_in[I_b2bb], sc + 528, sh + 528);

    // block2 conv3 1x1 (mma, fused affine from h2; o-tiles = 2)
    mma_conv_k<256, 128, 1, false, 4, 8, 256, 256, 256, 256, 1, 1>
        <<<dim3(NP2 / 128, 2), 256, SM256V>>>(
            nullptr, nullptr, h2, sc + 528, sh + 528,
            wc3_hi, wc3_lo, nullptr, w2, nullptr, ps, pq);
    bn_param<<<256, 256>>>(ps, pq, NP2 / 128, 256, 0, 1.f / NP2,
                           (const float*)d_in[I_b2gc], (const float*)d_in[I_b2bc], sc + 784, sh + 784);

    // tail
    maxfinP_k<<<256, 256>>>(w2, v2, sc + 784, sh + 784, sc + 1040, sh + 1040, gmax);
    fc_k<<<256, 256>>>(gmax, (const float*)d_in[I_fcw], (const float*)d_in[I_fcb], (float*)d_out);
}